// round 1
// baseline (speedup 1.0000x reference)
#include <cuda_runtime.h>

#define NA 50000
#define AFD 133
#define HID 128
#define NE 800000
#define NM 1024

// ---------------- scratch (device globals; no allocations allowed) ----------
__device__ float g_x[NA * HID];     // activations
__device__ float g_agg[NA * HID];   // aggregation / gemm2 out
__device__ float g_h[NA * HID];     // gemm1 out
__device__ int   g_deg[NA];
__device__ int   g_off[NA + 1];
__device__ int   g_pos[NA];
__device__ int   g_srclist[NE];
__device__ float g_sum[HID];
__device__ float g_sumsq[HID];

// ---------------- CSR build ----------------
__global__ void zero_csr_kernel() {
    int i = blockIdx.x * blockDim.x + threadIdx.x;
    int stride = gridDim.x * blockDim.x;
    for (int k = i; k < NA; k += stride) { g_deg[k] = 0; g_pos[k] = 0; }
}

__global__ void count_kernel(const int* __restrict__ ei) {
    int e = blockIdx.x * blockDim.x + threadIdx.x;
    if (e < NE) atomicAdd(&g_deg[ei[NE + e]], 1);
}

__global__ void scan_kernel() {
    __shared__ int sm[1024];
    int t = threadIdx.x;
    const int C = (NA + 1023) / 1024;  // 49 -> 49*1024 >= NA
    int start = t * C;
    int end = min((t + 1) * C, NA);
    int s = 0;
    for (int i = start; i < end; i++) s += g_deg[i];
    sm[t] = s;
    __syncthreads();
    for (int d = 1; d < 1024; d <<= 1) {
        int v = (t >= d) ? sm[t - d] : 0;
        __syncthreads();
        sm[t] += v;
        __syncthreads();
    }
    int run = (t > 0) ? sm[t - 1] : 0;
    for (int i = start; i < end; i++) { g_off[i] = run; run += g_deg[i]; }
    if (start < NA && end == NA) g_off[NA] = run;
}

__global__ void fill_kernel(const int* __restrict__ ei) {
    int e = blockIdx.x * blockDim.x + threadIdx.x;
    if (e < NE) {
        int tgt = ei[NE + e];
        int src = ei[e];
        int slot = atomicAdd(&g_pos[tgt], 1);
        g_srclist[g_off[tgt] + slot] = src;
    }
}

// ---------------- neighbor gather-sum (one warp per atom) ----------------
// Also zeroes the BN stats buffers for this depth (block 0), since gemm2
// (which accumulates them) runs strictly after this kernel in the stream.
__global__ void gather_kernel(const float* __restrict__ epsp, int d) {
    if (blockIdx.x == 0 && threadIdx.x < 2 * HID) {
        if (threadIdx.x < HID) g_sum[threadIdx.x] = 0.f;
        else g_sumsq[threadIdx.x - HID] = 0.f;
    }
    int gw = (blockIdx.x * blockDim.x + threadIdx.x) >> 5;
    int lane = threadIdx.x & 31;
    if (gw >= NA) return;
    float scale = 1.f + epsp[d];
    const float4* x4 = (const float4*)g_x;
    float4 acc = x4[gw * 32 + lane];
    acc.x *= scale; acc.y *= scale; acc.z *= scale; acc.w *= scale;
    int j = g_off[gw];
    int e = g_off[gw + 1];
    for (; j + 4 <= e; j += 4) {
        int s0 = g_srclist[j], s1 = g_srclist[j + 1];
        int s2 = g_srclist[j + 2], s3 = g_srclist[j + 3];
        float4 v0 = x4[s0 * 32 + lane];
        float4 v1 = x4[s1 * 32 + lane];
        float4 v2 = x4[s2 * 32 + lane];
        float4 v3 = x4[s3 * 32 + lane];
        acc.x += (v0.x + v1.x) + (v2.x + v3.x);
        acc.y += (v0.y + v1.y) + (v2.y + v3.y);
        acc.z += (v0.z + v1.z) + (v2.z + v3.z);
        acc.w += (v0.w + v1.w) + (v2.w + v3.w);
    }
    for (; j < e; j++) {
        int s = g_srclist[j];
        float4 v = x4[s * 32 + lane];
        acc.x += v.x; acc.y += v.y; acc.z += v.z; acc.w += v.w;
    }
    ((float4*)g_agg)[gw * 32 + lane] = acc;
}

// ---------------- GEMM: C[N,128] = op(A[N,K] @ W[K,128] + b) ---------------
// 128x128 tile, BK=32, 256 threads, 8x8 register blocking.
template <bool RELU, bool STATS>
__global__ __launch_bounds__(256)
void gemm_kernel(const float* __restrict__ A, const float* __restrict__ W,
                 const float* __restrict__ bias, float* __restrict__ C, int K) {
    __shared__ float As[128][33];
    __shared__ float Ws[32][128];
    int tid = threadIdx.x;
    int tx = tid & 15;    // column group (8 cols)
    int ty = tid >> 4;    // row group (8 rows)
    int rowBase = blockIdx.x * 128;

    float acc[8][8];
#pragma unroll
    for (int i = 0; i < 8; i++)
#pragma unroll
        for (int j = 0; j < 8; j++) acc[i][j] = 0.f;

    for (int k0 = 0; k0 < K; k0 += 32) {
#pragma unroll
        for (int e = tid; e < 128 * 32; e += 256) {
            int r = e >> 5, kk = e & 31;
            int gr = rowBase + r, gk = k0 + kk;
            float v = 0.f;
            if (gr < NA && gk < K) v = A[gr * K + gk];
            As[r][kk] = v;
        }
#pragma unroll
        for (int e = tid; e < 32 * 128; e += 256) {
            int kk = e >> 7, c = e & 127;
            int gk = k0 + kk;
            Ws[kk][c] = (gk < K) ? W[gk * HID + c] : 0.f;
        }
        __syncthreads();
#pragma unroll
        for (int kk = 0; kk < 32; kk++) {
            float a[8], w[8];
#pragma unroll
            for (int i = 0; i < 8; i++) a[i] = As[ty * 8 + i][kk];
#pragma unroll
            for (int j = 0; j < 8; j++) w[j] = Ws[kk][tx * 8 + j];
#pragma unroll
            for (int i = 0; i < 8; i++)
#pragma unroll
                for (int j = 0; j < 8; j++) acc[i][j] = fmaf(a[i], w[j], acc[i][j]);
        }
        __syncthreads();
    }

    float bj[8];
#pragma unroll
    for (int j = 0; j < 8; j++) bj[j] = bias[tx * 8 + j];
    float colSum[8], colSq[8];
#pragma unroll
    for (int j = 0; j < 8; j++) { colSum[j] = 0.f; colSq[j] = 0.f; }

#pragma unroll
    for (int i = 0; i < 8; i++) {
        int gr = rowBase + ty * 8 + i;
        if (gr < NA) {
            float v[8];
#pragma unroll
            for (int j = 0; j < 8; j++) {
                float t = acc[i][j] + bj[j];
                if (RELU) t = fmaxf(t, 0.f);
                v[j] = t;
                if (STATS) { colSum[j] += t; colSq[j] += t * t; }
            }
            float4* o = (float4*)&C[gr * HID + tx * 8];
            o[0] = make_float4(v[0], v[1], v[2], v[3]);
            o[1] = make_float4(v[4], v[5], v[6], v[7]);
        }
    }

    if (STATS) {
        // reduce block-local column sums in smem (reuse As: 4224 floats >= 4096)
        float* red = &As[0][0];
#pragma unroll
        for (int j = 0; j < 8; j++) {
            red[ty * 128 + tx * 8 + j] = colSum[j];
            red[2048 + ty * 128 + tx * 8 + j] = colSq[j];
        }
        __syncthreads();
        if (tid < 128) {
            float s = 0.f, q = 0.f;
#pragma unroll
            for (int r = 0; r < 16; r++) {
                s += red[r * 128 + tid];
                q += red[2048 + r * 128 + tid];
            }
            atomicAdd(&g_sum[tid], s);
            atomicAdd(&g_sumsq[tid], q);
        }
    }
}

// ---------------- BatchNorm + ReLU ----------------
__global__ void bn_relu_kernel(const float* __restrict__ gamma,
                               const float* __restrict__ beta) {
    int idx = blockIdx.x * blockDim.x + threadIdx.x;
    if (idx >= NA * HID) return;
    int c = idx & (HID - 1);
    const float invN = 1.f / (float)NA;
    float mean = g_sum[c] * invN;
    float var = g_sumsq[c] * invN - mean * mean;
    float inv = rsqrtf(var + 1e-5f);
    float v = gamma[c] * (g_agg[idx] - mean) * inv + beta[c];
    g_x[idx] = fmaxf(v, 0.f);
}

// ---------------- segment-mean pooling (segment_ids sorted) ----------------
__global__ void pool_kernel(const int* __restrict__ seg, float* __restrict__ out) {
    int m = blockIdx.x;
    int t = threadIdx.x;
    int lo = 0, hi = NA;
    while (lo < hi) { int mid = (lo + hi) >> 1; if (seg[mid] < m) lo = mid + 1; else hi = mid; }
    int start = lo;
    hi = NA;
    while (lo < hi) { int mid = (lo + hi) >> 1; if (seg[mid] < m + 1) lo = mid + 1; else hi = mid; }
    int end = lo;
    float s = 0.f;
    for (int a = start; a < end; a++) s += g_x[a * HID + t];
    int cnt = end - start;
    out[m * HID + t] = (cnt > 0) ? s / (float)cnt : 0.f;
}

// ---------------- launch ----------------
extern "C" void kernel_launch(void* const* d_in, const int* in_sizes, int n_in,
                              void* d_out, int out_size) {
    const float* f_atoms = (const float*)d_in[0];
    const float* W_in    = (const float*)d_in[1];
    const float* b_in    = (const float*)d_in[2];
    const float* W1      = (const float*)d_in[3];
    const float* b1      = (const float*)d_in[4];
    const float* W2      = (const float*)d_in[5];
    const float* b2      = (const float*)d_in[6];
    const float* gamma   = (const float*)d_in[7];
    const float* beta    = (const float*)d_in[8];
    const float* epsp    = (const float*)d_in[9];
    const int*   ei      = (const int*)d_in[10];
    const int*   seg     = (const int*)d_in[11];
    float* out = (float*)d_out;

    float *p_x, *p_agg, *p_h;
    cudaGetSymbolAddress((void**)&p_x, g_x);
    cudaGetSymbolAddress((void**)&p_agg, g_agg);
    cudaGetSymbolAddress((void**)&p_h, g_h);

    const int GEMM_BLOCKS = (NA + 127) / 128;  // 391
    const int EDGE_BLOCKS = (NE + 255) / 256;  // 3125

    // CSR build (reused for all 3 depths)
    zero_csr_kernel<<<98, 1024>>>();
    count_kernel<<<EDGE_BLOCKS, 256>>>(ei);
    scan_kernel<<<1, 1024>>>();
    fill_kernel<<<EDGE_BLOCKS, 256>>>(ei);

    // input projection: x = relu(f_atoms @ W_in + b_in)
    gemm_kernel<true, false><<<GEMM_BLOCKS, 256>>>(f_atoms, W_in, b_in, p_x, AFD);

    for (int d = 0; d < 3; d++) {
        gather_kernel<<<(NA + 7) / 8, 256>>>(epsp, d);  // agg = sum_nbr x + (1+eps)x; zeroes stats
        gemm_kernel<true, false><<<GEMM_BLOCKS, 256>>>(p_agg, W1 + d * HID * HID,
                                                       b1 + d * HID, p_h, HID);
        gemm_kernel<false, true><<<GEMM_BLOCKS, 256>>>(p_h, W2 + d * HID * HID,
                                                       b2 + d * HID, p_agg, HID);
        bn_relu_kernel<<<(NA * HID + 255) / 256, 256>>>(gamma + d * HID, beta + d * HID);
    }

    pool_kernel<<<NM, HID>>>(seg, out);
}

// round 4
// speedup vs baseline: 1.0724x; 1.0724x over previous
#include <cuda_runtime.h>
#include <cuda_bf16.h>
#include <cstdint>

#define NA 50000
#define AFD 133
#define HID 128
#define NE 800000
#define NM 1024
#define KPAD 192
#define NT ((NA + 127) / 128)

// row stride in smem: 64+8 bf16 = 144 bytes (16B aligned, ldmatrix conflict-free)
#define RSTRIDE 144
#define CHUNK (128 * RSTRIDE)

// ====================== helpers ======================
__device__ __forceinline__ uint32_t smem_u32(const void* p) {
    uint32_t a;
    asm("{ .reg .u64 t; cvta.to.shared.u64 t, %1; cvt.u32.u64 %0, t; }" : "=r"(a) : "l"(p));
    return a;
}
__device__ __forceinline__ void ldsm4(uint32_t* r, uint32_t addr) {
    asm volatile("ldmatrix.sync.aligned.m8n8.x4.shared.b16 {%0,%1,%2,%3}, [%4];"
                 : "=r"(r[0]), "=r"(r[1]), "=r"(r[2]), "=r"(r[3]) : "r"(addr));
}
__device__ __forceinline__ void mma16816(float* c, const uint32_t* a, const uint32_t* b) {
    asm volatile(
        "mma.sync.aligned.m16n8k16.row.col.f32.bf16.bf16.f32 "
        "{%0,%1,%2,%3}, {%4,%5,%6,%7}, {%8,%9}, {%0,%1,%2,%3};"
        : "+f"(c[0]), "+f"(c[1]), "+f"(c[2]), "+f"(c[3])
        : "r"(a[0]), "r"(a[1]), "r"(a[2]), "r"(a[3]), "r"(b[0]), "r"(b[1]));
}
__device__ __forceinline__ void split2(float v0, float v1, uint32_t& h, uint32_t& l) {
    __nv_bfloat16 h0 = __float2bfloat16(v0), h1 = __float2bfloat16(v1);
    __nv_bfloat16 l0 = __float2bfloat16(v0 - __bfloat162float(h0));
    __nv_bfloat16 l1 = __float2bfloat16(v1 - __bfloat162float(h1));
    h = ((uint32_t)__bfloat16_as_ushort(h1) << 16) | __bfloat16_as_ushort(h0);
    l = ((uint32_t)__bfloat16_as_ushort(l1) << 16) | __bfloat16_as_ushort(l0);
}

// ====================== scratch ======================
__device__ float g_x[NA * HID];
__device__ float g_agg[NA * HID];
__device__ __nv_bfloat16 g_fh[NA * KPAD], g_fl[NA * KPAD];
__device__ __nv_bfloat16 g_ah[NA * HID], g_al[NA * HID];
__device__ __nv_bfloat16 g_hh[NA * HID], g_hl[NA * HID];
__device__ __nv_bfloat16 g_wfh[HID * KPAD], g_wfl[HID * KPAD];
__device__ __nv_bfloat16 g_w1h[3 * HID * HID], g_w1l[3 * HID * HID];
__device__ __nv_bfloat16 g_w2h[3 * HID * HID], g_w2l[3 * HID * HID];
__device__ int g_deg[NA];
__device__ int g_off[NA + 1];
__device__ int g_pos[NA];
__device__ int g_srclist[NE];
__device__ float g_sum[HID];
__device__ float g_sumsq[HID];

// ====================== conversions ======================
__global__ void convert_atoms_kernel(const float* __restrict__ f) {
    int i = blockIdx.x * blockDim.x + threadIdx.x;
    int total = NA * (KPAD / 2);
    if (i >= total) return;
    int row = i / (KPAD / 2), p = i % (KPAD / 2);
    int k = 2 * p;
    float v0 = (k < AFD) ? f[row * AFD + k] : 0.f;
    float v1 = (k + 1 < AFD) ? f[row * AFD + k + 1] : 0.f;
    uint32_t h, l;
    split2(v0, v1, h, l);
    ((uint32_t*)g_fh)[row * (KPAD / 2) + p] = h;
    ((uint32_t*)g_fl)[row * (KPAD / 2) + p] = l;
}

__global__ void prep_weights_kernel(const float* __restrict__ W_in,
                                    const float* __restrict__ W1,
                                    const float* __restrict__ W2) {
    int i = blockIdx.x * blockDim.x + threadIdx.x;
    int stride = gridDim.x * blockDim.x;
    for (int idx = i; idx < HID * KPAD; idx += stride) {
        int n = idx / KPAD, k = idx % KPAD;
        float v = (k < AFD) ? W_in[k * HID + n] : 0.f;
        __nv_bfloat16 h = __float2bfloat16(v);
        g_wfh[idx] = h;
        g_wfl[idx] = __float2bfloat16(v - __bfloat162float(h));
    }
    for (int idx = i; idx < 3 * HID * HID; idx += stride) {
        int d = idx / (HID * HID);
        int r = idx % (HID * HID);
        int n = r / HID, k = r % HID;
        float v1 = W1[d * HID * HID + k * HID + n];
        float v2 = W2[d * HID * HID + k * HID + n];
        __nv_bfloat16 h1 = __float2bfloat16(v1);
        g_w1h[idx] = h1;
        g_w1l[idx] = __float2bfloat16(v1 - __bfloat162float(h1));
        __nv_bfloat16 h2 = __float2bfloat16(v2);
        g_w2h[idx] = h2;
        g_w2l[idx] = __float2bfloat16(v2 - __bfloat162float(h2));
    }
}

// ====================== CSR build ======================
__global__ void zero_csr_kernel() {
    int i = blockIdx.x * blockDim.x + threadIdx.x;
    int stride = gridDim.x * blockDim.x;
    for (int k = i; k < NA; k += stride) { g_deg[k] = 0; g_pos[k] = 0; }
}
__global__ void count_kernel(const int* __restrict__ ei) {
    int e = blockIdx.x * blockDim.x + threadIdx.x;
    if (e < NE) atomicAdd(&g_deg[ei[NE + e]], 1);
}
__global__ void scan_kernel() {
    __shared__ int sm[1024];
    int t = threadIdx.x;
    const int C = (NA + 1023) / 1024;
    int start = t * C;
    int end = min((t + 1) * C, NA);
    int s = 0;
    for (int i = start; i < end; i++) s += g_deg[i];
    sm[t] = s;
    __syncthreads();
    for (int d = 1; d < 1024; d <<= 1) {
        int v = (t >= d) ? sm[t - d] : 0;
        __syncthreads();
        sm[t] += v;
        __syncthreads();
    }
    int run = (t > 0) ? sm[t - 1] : 0;
    for (int i = start; i < end; i++) { g_off[i] = run; run += g_deg[i]; }
    if (start < NA && end == NA) g_off[NA] = run;
}
__global__ void fill_kernel(const int* __restrict__ ei) {
    int e = blockIdx.x * blockDim.x + threadIdx.x;
    if (e < NE) {
        int tgt = ei[NE + e];
        int src = ei[e];
        int slot = atomicAdd(&g_pos[tgt], 1);
        g_srclist[g_off[tgt] + slot] = src;
    }
}

// ====================== gather ======================
__global__ void gather_kernel(const float* __restrict__ epsp, int d) {
    if (blockIdx.x == 0 && threadIdx.x < 2 * HID) {
        if (threadIdx.x < HID) g_sum[threadIdx.x] = 0.f;
        else g_sumsq[threadIdx.x - HID] = 0.f;
    }
    int gw = (blockIdx.x * blockDim.x + threadIdx.x) >> 5;
    int lane = threadIdx.x & 31;
    if (gw >= NA) return;
    float scale = 1.f + epsp[d];
    const float4* x4 = (const float4*)g_x;
    float4 acc = x4[gw * 32 + lane];
    acc.x *= scale; acc.y *= scale; acc.z *= scale; acc.w *= scale;
    int j = g_off[gw];
    int e = g_off[gw + 1];
    for (; j + 4 <= e; j += 4) {
        int s0 = g_srclist[j], s1 = g_srclist[j + 1];
        int s2 = g_srclist[j + 2], s3 = g_srclist[j + 3];
        float4 v0 = x4[s0 * 32 + lane];
        float4 v1 = x4[s1 * 32 + lane];
        float4 v2 = x4[s2 * 32 + lane];
        float4 v3 = x4[s3 * 32 + lane];
        acc.x += (v0.x + v1.x) + (v2.x + v3.x);
        acc.y += (v0.y + v1.y) + (v2.y + v3.y);
        acc.z += (v0.z + v1.z) + (v2.z + v3.z);
        acc.w += (v0.w + v1.w) + (v2.w + v3.w);
    }
    for (; j < e; j++) {
        int s = g_srclist[j];
        float4 v = x4[s * 32 + lane];
        acc.x += v.x; acc.y += v.y; acc.z += v.z; acc.w += v.w;
    }
    uint32_t h01, l01, h23, l23;
    split2(acc.x, acc.y, h01, l01);
    split2(acc.z, acc.w, h23, l23);
    ((uint2*)g_ah)[gw * 32 + lane] = make_uint2(h01, h23);
    ((uint2*)g_al)[gw * 32 + lane] = make_uint2(l01, l23);
}

// ====================== bf16x3 mma.sync GEMM ======================
// C[NA,128] = A[NA,K] @ W[K,128] + b.  A,W as bf16 hi/lo, W pre-transposed [128(N)][K].
// 256 threads = 8 warps (2M x 4N); CTA tile 128x128; warp tile 64x32.
template <int KC, bool RELU, bool OUTBF>
__global__ __launch_bounds__(256, 1) void mma_gemm_kernel(
    const __nv_bfloat16* __restrict__ Ah, const __nv_bfloat16* __restrict__ Al,
    const __nv_bfloat16* __restrict__ Wh, const __nv_bfloat16* __restrict__ Wl,
    const float* __restrict__ bias,
    float* __restrict__ Cf, __nv_bfloat16* __restrict__ Ch, __nv_bfloat16* __restrict__ Cl) {
    extern __shared__ char smem[];
    const int K = KC * 64;
    const uint32_t OFF_WH = 512;
    const uint32_t OFF_WL = OFF_WH + KC * CHUNK;
    const uint32_t OFF_AH = OFF_WL + KC * CHUNK;
    const uint32_t OFF_AL = OFF_AH + KC * CHUNK;
    const uint32_t sb = smem_u32(smem);

    int tid = threadIdx.x;
    int wid = tid >> 5, lane = tid & 31;
    int warpM = wid & 1, warpN = wid >> 1;

    float* bias_s = (float*)smem;
    if (tid < HID) bias_s[tid] = bias[tid];

    // load W hi/lo once (resident for whole persistent CTA)
    for (int e = tid; e < KC * 2048; e += 256) {
        int c = e >> 11, q = e & 2047;
        int m = q >> 10;            // 0 = hi, 1 = lo
        int r = (q >> 3) & 127, p = q & 7;
        const __nv_bfloat16* src = m ? Wl : Wh;
        uint4 v = *(const uint4*)(src + r * K + c * 64 + p * 8);
        uint32_t off = (m ? OFF_WL : OFF_WH) + c * CHUNK + r * RSTRIDE + p * 16;
        *(uint4*)(smem + off) = v;
    }
    __syncthreads();

    for (int t = blockIdx.x; t < NT; t += gridDim.x) {
        int rbase = t * 128;
        // load A tile hi/lo
        for (int e = tid; e < KC * 2048; e += 256) {
            int c = e >> 11, q = e & 2047;
            int m = q >> 10;
            int r = (q >> 3) & 127, p = q & 7;
            int grow = rbase + r;
            const __nv_bfloat16* src = m ? Al : Ah;
            uint4 v = make_uint4(0, 0, 0, 0);
            if (grow < NA) v = *(const uint4*)(src + grow * K + c * 64 + p * 8);
            uint32_t off = (m ? OFF_AL : OFF_AH) + c * CHUNK + r * RSTRIDE + p * 16;
            *(uint4*)(smem + off) = v;
        }
        __syncthreads();

        float acc[4][4][4];
#pragma unroll
        for (int mf = 0; mf < 4; mf++)
#pragma unroll
            for (int nf = 0; nf < 4; nf++)
#pragma unroll
                for (int r = 0; r < 4; r++) acc[mf][nf][r] = 0.f;

        // ldmatrix lane address components
        int aRow = warpM * 64 + (lane & 15);
        int aCol = (lane >> 4) * 8;           // bf16 units
        int bRow = warpN * 32 + ((lane >> 4) * 8) + (lane & 7);
        int bCol = ((lane >> 3) & 1) * 8;

#pragma unroll
        for (int c = 0; c < KC; c++) {
            uint32_t baseA = sb + c * CHUNK;
            uint32_t baseW = sb + c * CHUNK;
#pragma unroll
            for (int kk = 0; kk < 4; kk++) {
                int k0 = kk * 16;
                uint32_t ah[4][4], al[4][4], wh[2][4], wl[2][4];
#pragma unroll
                for (int mf = 0; mf < 4; mf++) {
                    uint32_t ad = (aRow + mf * 16) * RSTRIDE + (k0 + aCol) * 2;
                    ldsm4(ah[mf], baseA + OFF_AH + ad);
                    ldsm4(al[mf], baseA + OFF_AL + ad);
                }
#pragma unroll
                for (int nf2 = 0; nf2 < 2; nf2++) {
                    uint32_t wd = (bRow + nf2 * 16) * RSTRIDE + (k0 + bCol) * 2;
                    ldsm4(wh[nf2], baseW + OFF_WH + wd);
                    ldsm4(wl[nf2], baseW + OFF_WL + wd);
                }
#pragma unroll
                for (int mf = 0; mf < 4; mf++)
#pragma unroll
                    for (int nf = 0; nf < 4; nf++) {
                        uint32_t* bh = &wh[nf >> 1][(nf & 1) * 2];
                        uint32_t* bl = &wl[nf >> 1][(nf & 1) * 2];
                        mma16816(acc[mf][nf], ah[mf], bh);
                        mma16816(acc[mf][nf], ah[mf], bl);
                        mma16816(acc[mf][nf], al[mf], bh);
                    }
            }
        }

        // epilogue: registers -> global
#pragma unroll
        for (int mf = 0; mf < 4; mf++) {
            int r0 = rbase + warpM * 64 + mf * 16 + (lane >> 2);
#pragma unroll
            for (int half = 0; half < 2; half++) {
                int row = r0 + half * 8;
                if (row >= NA) continue;
#pragma unroll
                for (int nf = 0; nf < 4; nf++) {
                    int col = warpN * 32 + nf * 8 + 2 * (lane & 3);
                    float v0 = acc[mf][nf][half * 2 + 0] + bias_s[col];
                    float v1 = acc[mf][nf][half * 2 + 1] + bias_s[col + 1];
                    if (RELU) { v0 = fmaxf(v0, 0.f); v1 = fmaxf(v1, 0.f); }
                    if (OUTBF) {
                        uint32_t h, l;
                        split2(v0, v1, h, l);
                        *(uint32_t*)(Ch + row * HID + col) = h;
                        *(uint32_t*)(Cl + row * HID + col) = l;
                    } else {
                        *(float2*)(Cf + row * HID + col) = make_float2(v0, v1);
                    }
                }
            }
        }
        __syncthreads();
    }
}

// ====================== BN stats + BN/ReLU ======================
__global__ void stats_kernel() {
    int col = threadIdx.x;
    float s = 0.f, q = 0.f;
    for (int r = blockIdx.x; r < NA; r += gridDim.x) {
        float v = g_agg[r * HID + col];
        s += v;
        q += v * v;
    }
    atomicAdd(&g_sum[col], s);
    atomicAdd(&g_sumsq[col], q);
}

__global__ void bn_relu_kernel(const float* __restrict__ gamma,
                               const float* __restrict__ beta) {
    int idx = blockIdx.x * blockDim.x + threadIdx.x;
    if (idx >= NA * HID) return;
    int c = idx & (HID - 1);
    const float invN = 1.f / (float)NA;
    float mean = g_sum[c] * invN;
    float var = g_sumsq[c] * invN - mean * mean;
    float inv = rsqrtf(var + 1e-5f);
    float v = gamma[c] * (g_agg[idx] - mean) * inv + beta[c];
    g_x[idx] = fmaxf(v, 0.f);
}

// ====================== pooling ======================
__global__ void pool_kernel(const int* __restrict__ seg, float* __restrict__ out) {
    int m = blockIdx.x;
    int t = threadIdx.x;
    int lo = 0, hi = NA;
    while (lo < hi) { int mid = (lo + hi) >> 1; if (seg[mid] < m) lo = mid + 1; else hi = mid; }
    int start = lo;
    hi = NA;
    while (lo < hi) { int mid = (lo + hi) >> 1; if (seg[mid] < m + 1) lo = mid + 1; else hi = mid; }
    int end = lo;
    float s = 0.f;
    for (int a = start; a < end; a++) s += g_x[a * HID + t];
    int cnt = end - start;
    out[m * HID + t] = (cnt > 0) ? s / (float)cnt : 0.f;
}

// ====================== launch ======================
extern "C" void kernel_launch(void* const* d_in, const int* in_sizes, int n_in,
                              void* d_out, int out_size) {
    const float* f_atoms = (const float*)d_in[0];
    const float* W_in    = (const float*)d_in[1];
    const float* b_in    = (const float*)d_in[2];
    const float* W1      = (const float*)d_in[3];
    const float* b1      = (const float*)d_in[4];
    const float* W2      = (const float*)d_in[5];
    const float* b2      = (const float*)d_in[6];
    const float* gamma   = (const float*)d_in[7];
    const float* beta    = (const float*)d_in[8];
    const float* epsp    = (const float*)d_in[9];
    const int*   ei      = (const int*)d_in[10];
    const int*   seg     = (const int*)d_in[11];
    float* out = (float*)d_out;

    float *p_x, *p_agg;
    __nv_bfloat16 *p_fh, *p_fl, *p_ah, *p_al, *p_hh, *p_hl;
    __nv_bfloat16 *p_wfh, *p_wfl, *p_w1h, *p_w1l, *p_w2h, *p_w2l;
    cudaGetSymbolAddress((void**)&p_x, g_x);
    cudaGetSymbolAddress((void**)&p_agg, g_agg);
    cudaGetSymbolAddress((void**)&p_fh, g_fh);
    cudaGetSymbolAddress((void**)&p_fl, g_fl);
    cudaGetSymbolAddress((void**)&p_ah, g_ah);
    cudaGetSymbolAddress((void**)&p_al, g_al);
    cudaGetSymbolAddress((void**)&p_hh, g_hh);
    cudaGetSymbolAddress((void**)&p_hl, g_hl);
    cudaGetSymbolAddress((void**)&p_wfh, g_wfh);
    cudaGetSymbolAddress((void**)&p_wfl, g_wfl);
    cudaGetSymbolAddress((void**)&p_w1h, g_w1h);
    cudaGetSymbolAddress((void**)&p_w1l, g_w1l);
    cudaGetSymbolAddress((void**)&p_w2h, g_w2h);
    cudaGetSymbolAddress((void**)&p_w2l, g_w2l);

    const int SMEM2 = 512 + 4 * 2 * CHUNK;  // 147968
    const int SMEM3 = 512 + 4 * 3 * CHUNK;  // 221696
    cudaFuncSetAttribute(mma_gemm_kernel<3, true, false>,
                         cudaFuncAttributeMaxDynamicSharedMemorySize, SMEM3);
    cudaFuncSetAttribute(mma_gemm_kernel<2, true, true>,
                         cudaFuncAttributeMaxDynamicSharedMemorySize, SMEM2);
    cudaFuncSetAttribute(mma_gemm_kernel<2, false, false>,
                         cudaFuncAttributeMaxDynamicSharedMemorySize, SMEM2);

    const int EDGE_BLOCKS = (NE + 255) / 256;

    zero_csr_kernel<<<98, 1024>>>();
    count_kernel<<<EDGE_BLOCKS, 256>>>(ei);
    scan_kernel<<<1, 1024>>>();
    fill_kernel<<<EDGE_BLOCKS, 256>>>(ei);
    prep_weights_kernel<<<96, 256>>>(W_in, W1, W2);
    convert_atoms_kernel<<<(NA * (KPAD / 2) + 255) / 256, 256>>>(f_atoms);

    // input projection: x = relu(f_atoms @ W_in + b_in)  (fp32 out for gather)
    mma_gemm_kernel<3, true, false><<<148, 256, SMEM3>>>(
        p_fh, p_fl, p_wfh, p_wfl, b_in, p_x, nullptr, nullptr);

    for (int d = 0; d < 3; d++) {
        gather_kernel<<<(NA + 7) / 8, 256>>>(epsp, d);
        mma_gemm_kernel<2, true, true><<<148, 256, SMEM2>>>(
            p_ah, p_al, p_w1h + d * HID * HID, p_w1l + d * HID * HID,
            b1 + d * HID, nullptr, p_hh, p_hl);
        mma_gemm_kernel<2, false, false><<<148, 256, SMEM2>>>(
            p_hh, p_hl, p_w2h + d * HID * HID, p_w2l + d * HID * HID,
            b2 + d * HID, p_agg, nullptr, nullptr);
        stats_kernel<<<256, 128>>>();
        bn_relu_kernel<<<(NA * HID + 255) / 256, 256>>>(gamma + d * HID, beta + d * HID);
    }

    pool_kernel<<<NM, HID>>>(seg, out);
}

// round 5
// speedup vs baseline: 1.1977x; 1.1168x over previous
#include <cuda_runtime.h>
#include <cuda_bf16.h>
#include <cstdint>

#define NA 50000
#define AFD 133
#define HID 128
#define NE 800000
#define NM 1024
#define KPAD 192
#define NT ((NA + 127) / 128)

// row stride in smem: 64+8 bf16 = 144 bytes (16B aligned, ldmatrix conflict-free)
#define RSTRIDE 144
#define CHUNK (128 * RSTRIDE)

// ====================== helpers ======================
__device__ __forceinline__ uint32_t smem_u32(const void* p) {
    uint32_t a;
    asm("{ .reg .u64 t; cvta.to.shared.u64 t, %1; cvt.u32.u64 %0, t; }" : "=r"(a) : "l"(p));
    return a;
}
__device__ __forceinline__ void ldsm4(uint32_t* r, uint32_t addr) {
    asm volatile("ldmatrix.sync.aligned.m8n8.x4.shared.b16 {%0,%1,%2,%3}, [%4];"
                 : "=r"(r[0]), "=r"(r[1]), "=r"(r[2]), "=r"(r[3]) : "r"(addr));
}
__device__ __forceinline__ void mma16816(float* c, const uint32_t* a, const uint32_t* b) {
    asm volatile(
        "mma.sync.aligned.m16n8k16.row.col.f32.bf16.bf16.f32 "
        "{%0,%1,%2,%3}, {%4,%5,%6,%7}, {%8,%9}, {%0,%1,%2,%3};"
        : "+f"(c[0]), "+f"(c[1]), "+f"(c[2]), "+f"(c[3])
        : "r"(a[0]), "r"(a[1]), "r"(a[2]), "r"(a[3]), "r"(b[0]), "r"(b[1]));
}
__device__ __forceinline__ void cp_async16(uint32_t dst, const void* src, uint32_t bytes) {
    asm volatile("cp.async.cg.shared.global [%0], [%1], 16, %2;"
                 :: "r"(dst), "l"(src), "r"(bytes));
}
#define CP_COMMIT() asm volatile("cp.async.commit_group;" ::: "memory")
#define CP_WAIT0()  asm volatile("cp.async.wait_group 0;" ::: "memory")

__device__ __forceinline__ void split2(float v0, float v1, uint32_t& h, uint32_t& l) {
    __nv_bfloat16 h0 = __float2bfloat16(v0), h1 = __float2bfloat16(v1);
    __nv_bfloat16 l0 = __float2bfloat16(v0 - __bfloat162float(h0));
    __nv_bfloat16 l1 = __float2bfloat16(v1 - __bfloat162float(h1));
    h = ((uint32_t)__bfloat16_as_ushort(h1) << 16) | __bfloat16_as_ushort(h0);
    l = ((uint32_t)__bfloat16_as_ushort(l1) << 16) | __bfloat16_as_ushort(l0);
}

// ====================== scratch ======================
__device__ float g_x[NA * HID];
__device__ float g_agg[NA * HID];
__device__ __nv_bfloat16 g_fh[NA * KPAD], g_fl[NA * KPAD];
__device__ __nv_bfloat16 g_ah[NA * HID], g_al[NA * HID];
__device__ __nv_bfloat16 g_hh[NA * HID], g_hl[NA * HID];
__device__ __nv_bfloat16 g_wfh[HID * KPAD], g_wfl[HID * KPAD];
__device__ __nv_bfloat16 g_w1h[3 * HID * HID], g_w1l[3 * HID * HID];
__device__ __nv_bfloat16 g_w2h[3 * HID * HID], g_w2l[3 * HID * HID];
__device__ int g_deg[NA];
__device__ int g_off[NA + 1];
__device__ int g_pos[NA];
__device__ int g_srclist[NE];
__device__ float g_sumA[2][HID];
__device__ float g_sumsqA[2][HID];

// ====================== conversions ======================
__global__ void convert_atoms_kernel(const float* __restrict__ f) {
    int i = blockIdx.x * blockDim.x + threadIdx.x;
    int total = NA * (KPAD / 2);
    if (i >= total) return;
    int row = i / (KPAD / 2), p = i % (KPAD / 2);
    int k = 2 * p;
    float v0 = (k < AFD) ? f[row * AFD + k] : 0.f;
    float v1 = (k + 1 < AFD) ? f[row * AFD + k + 1] : 0.f;
    uint32_t h, l;
    split2(v0, v1, h, l);
    ((uint32_t*)g_fh)[row * (KPAD / 2) + p] = h;
    ((uint32_t*)g_fl)[row * (KPAD / 2) + p] = l;
}

__global__ void prep_weights_kernel(const float* __restrict__ W_in,
                                    const float* __restrict__ W1,
                                    const float* __restrict__ W2) {
    int i = blockIdx.x * blockDim.x + threadIdx.x;
    int stride = gridDim.x * blockDim.x;
    for (int idx = i; idx < HID * KPAD; idx += stride) {
        int n = idx / KPAD, k = idx % KPAD;
        float v = (k < AFD) ? W_in[k * HID + n] : 0.f;
        __nv_bfloat16 h = __float2bfloat16(v);
        g_wfh[idx] = h;
        g_wfl[idx] = __float2bfloat16(v - __bfloat162float(h));
    }
    for (int idx = i; idx < 3 * HID * HID; idx += stride) {
        int d = idx / (HID * HID);
        int r = idx % (HID * HID);
        int n = r / HID, k = r % HID;
        float v1 = W1[d * HID * HID + k * HID + n];
        float v2 = W2[d * HID * HID + k * HID + n];
        __nv_bfloat16 h1 = __float2bfloat16(v1);
        g_w1h[idx] = h1;
        g_w1l[idx] = __float2bfloat16(v1 - __bfloat162float(h1));
        __nv_bfloat16 h2 = __float2bfloat16(v2);
        g_w2h[idx] = h2;
        g_w2l[idx] = __float2bfloat16(v2 - __bfloat162float(h2));
    }
}

// ====================== CSR build ======================
__global__ void zero_csr_kernel() {
    int i = blockIdx.x * blockDim.x + threadIdx.x;
    int stride = gridDim.x * blockDim.x;
    for (int k = i; k < NA; k += stride) { g_deg[k] = 0; g_pos[k] = 0; }
}
__global__ void count_kernel(const int* __restrict__ ei) {
    int e = blockIdx.x * blockDim.x + threadIdx.x;
    if (e < NE) atomicAdd(&g_deg[ei[NE + e]], 1);
}
__global__ void scan_kernel() {
    __shared__ int sm[1024];
    int t = threadIdx.x;
    const int C = (NA + 1023) / 1024;
    int start = t * C;
    int end = min((t + 1) * C, NA);
    int s = 0;
    for (int i = start; i < end; i++) s += g_deg[i];
    sm[t] = s;
    __syncthreads();
    for (int d = 1; d < 1024; d <<= 1) {
        int v = (t >= d) ? sm[t - d] : 0;
        __syncthreads();
        sm[t] += v;
        __syncthreads();
    }
    int run = (t > 0) ? sm[t - 1] : 0;
    for (int i = start; i < end; i++) { g_off[i] = run; run += g_deg[i]; }
    if (start < NA && end == NA) g_off[NA] = run;
}
__global__ void fill_kernel(const int* __restrict__ ei) {
    int e = blockIdx.x * blockDim.x + threadIdx.x;
    if (e < NE) {
        int tgt = ei[NE + e];
        int src = ei[e];
        int slot = atomicAdd(&g_pos[tgt], 1);
        g_srclist[g_off[tgt] + slot] = src;
    }
}

// ====================== gather (+fused BN/ReLU of previous depth) ==========
// reads SRC fp32 rows; if BN: v <- relu(v*scale_c + shift_c) per element.
// acc = sum_nbr v[src] + (1+eps)*v[self];  writes bf16 hi/lo for GEMM1.
// Also zeroes the stats slot `zslot` (block 0).
template <bool BN>
__global__ void gather_kernel(const float* __restrict__ src_arr,
                              const float* __restrict__ epsp, int d,
                              const float* __restrict__ gamma,
                              const float* __restrict__ beta,
                              int rslot, int zslot) {
    if (blockIdx.x == 0 && threadIdx.x < 2 * HID) {
        if (threadIdx.x < HID) g_sumA[zslot][threadIdx.x] = 0.f;
        else g_sumsqA[zslot][threadIdx.x - HID] = 0.f;
    }
    int gw = (blockIdx.x * blockDim.x + threadIdx.x) >> 5;
    int lane = threadIdx.x & 31;
    if (gw >= NA) return;

    float4 bsc = make_float4(0.f, 0.f, 0.f, 0.f), bsh = make_float4(0.f, 0.f, 0.f, 0.f);
    if (BN) {
        const float invN = 1.f / (float)NA;
        int c0 = lane * 4;
#pragma unroll
        for (int q = 0; q < 4; q++) {
            int c = c0 + q;
            float mean = g_sumA[rslot][c] * invN;
            float var = g_sumsqA[rslot][c] * invN - mean * mean;
            float sc = gamma[c] * rsqrtf(var + 1e-5f);
            float sh = beta[c] - mean * sc;
            ((float*)&bsc)[q] = sc;
            ((float*)&bsh)[q] = sh;
        }
    }
    float scale = 1.f + epsp[d];
    const float4* x4 = (const float4*)src_arr;

    auto loadrow = [&](int r) -> float4 {
        float4 v = x4[r * 32 + lane];
        if (BN) {
            v.x = fmaxf(fmaf(v.x, bsc.x, bsh.x), 0.f);
            v.y = fmaxf(fmaf(v.y, bsc.y, bsh.y), 0.f);
            v.z = fmaxf(fmaf(v.z, bsc.z, bsh.z), 0.f);
            v.w = fmaxf(fmaf(v.w, bsc.w, bsh.w), 0.f);
        }
        return v;
    };

    float4 acc = loadrow(gw);
    acc.x *= scale; acc.y *= scale; acc.z *= scale; acc.w *= scale;
    int j = g_off[gw];
    int e = g_off[gw + 1];
    for (; j + 4 <= e; j += 4) {
        int s0 = g_srclist[j], s1 = g_srclist[j + 1];
        int s2 = g_srclist[j + 2], s3 = g_srclist[j + 3];
        float4 v0 = loadrow(s0), v1 = loadrow(s1), v2 = loadrow(s2), v3 = loadrow(s3);
        acc.x += (v0.x + v1.x) + (v2.x + v3.x);
        acc.y += (v0.y + v1.y) + (v2.y + v3.y);
        acc.z += (v0.z + v1.z) + (v2.z + v3.z);
        acc.w += (v0.w + v1.w) + (v2.w + v3.w);
    }
    for (; j < e; j++) {
        float4 v = loadrow(g_srclist[j]);
        acc.x += v.x; acc.y += v.y; acc.z += v.z; acc.w += v.w;
    }
    uint32_t h01, l01, h23, l23;
    split2(acc.x, acc.y, h01, l01);
    split2(acc.z, acc.w, h23, l23);
    ((uint2*)g_ah)[gw * 32 + lane] = make_uint2(h01, h23);
    ((uint2*)g_al)[gw * 32 + lane] = make_uint2(l01, l23);
}

// ====================== bf16x3 mma.sync GEMM ======================
// C[NA,128] = A[NA,K] @ W[K,128] + b.  A,W as bf16 hi/lo, W pre-transposed [128(N)][K].
// 256 threads = 8 warps (2M x 4N); CTA tile 128x128; warp tile 64x32.
// DB: cp.async double-buffered A tiles (KC==2 only).
template <int KC, bool DB, bool RELU, bool OUTBF>
__global__ __launch_bounds__(256, 1) void mma_gemm_kernel(
    const __nv_bfloat16* __restrict__ Ah, const __nv_bfloat16* __restrict__ Al,
    const __nv_bfloat16* __restrict__ Wh, const __nv_bfloat16* __restrict__ Wl,
    const float* __restrict__ bias,
    float* __restrict__ Cf, __nv_bfloat16* __restrict__ Ch, __nv_bfloat16* __restrict__ Cl) {
    extern __shared__ char smem[];
    const int K = KC * 64;
    const uint32_t OFF_WH = 512;
    const uint32_t OFF_WL = OFF_WH + KC * CHUNK;
    const uint32_t OFF_A0H = OFF_WL + KC * CHUNK;
    const uint32_t OFF_A0L = OFF_A0H + KC * CHUNK;
    const uint32_t OFF_A1H = OFF_A0L + KC * CHUNK;  // DB only
    const uint32_t OFF_A1L = OFF_A1H + KC * CHUNK;  // DB only
    const uint32_t sb = smem_u32(smem);

    int tid = threadIdx.x;
    int wid = tid >> 5, lane = tid & 31;
    int warpM = wid & 1, warpN = wid >> 1;

    float* bias_s = (float*)smem;
    if (tid < HID) bias_s[tid] = bias[tid];

    // load W hi/lo once (resident for whole persistent CTA)
    for (int e = tid; e < KC * 2048; e += 256) {
        int c = e >> 11, q = e & 2047;
        int m = q >> 10;
        int r = (q >> 3) & 127, p = q & 7;
        const __nv_bfloat16* src = m ? Wl : Wh;
        uint4 v = *(const uint4*)(src + r * K + c * 64 + p * 8);
        uint32_t off = (m ? OFF_WL : OFF_WH) + c * CHUNK + r * RSTRIDE + p * 16;
        *(uint4*)(smem + off) = v;
    }

    // ldmatrix lane address components
    int aRow = warpM * 64 + (lane & 15);
    int aCol = (lane >> 4) * 8;
    int bRow = warpN * 32 + ((lane >> 4) * 8) + (lane & 7);
    int bCol = ((lane >> 3) & 1) * 8;

    auto issue_tile = [&](int rbase, uint32_t offAH, uint32_t offAL) {
#pragma unroll
        for (int e = tid; e < KC * 2048; e += 256) {
            int c = e >> 11, q = e & 2047;
            int m = q >> 10;
            int r = (q >> 3) & 127, p = q & 7;
            int grow = rbase + r;
            const __nv_bfloat16* src = m ? Al : Ah;
            int sg = grow < NA ? grow : NA - 1;
            uint32_t bytes = grow < NA ? 16u : 0u;
            uint32_t off = (m ? offAL : offAH) + c * CHUNK + r * RSTRIDE + p * 16;
            cp_async16(sb + off, src + sg * K + c * 64 + p * 8, bytes);
        }
        CP_COMMIT();
    };

    auto compute_store = [&](int rbase, uint32_t offAH, uint32_t offAL) {
        float acc[4][4][4];
#pragma unroll
        for (int mf = 0; mf < 4; mf++)
#pragma unroll
            for (int nf = 0; nf < 4; nf++)
#pragma unroll
                for (int r = 0; r < 4; r++) acc[mf][nf][r] = 0.f;
#pragma unroll
        for (int c = 0; c < KC; c++) {
#pragma unroll
            for (int kk = 0; kk < 4; kk++) {
                int k0 = kk * 16;
                uint32_t ah[4][4], al[4][4], wh[2][4], wl[2][4];
#pragma unroll
                for (int mf = 0; mf < 4; mf++) {
                    uint32_t ad = (aRow + mf * 16) * RSTRIDE + (k0 + aCol) * 2 + c * CHUNK;
                    ldsm4(ah[mf], sb + offAH + ad);
                    ldsm4(al[mf], sb + offAL + ad);
                }
#pragma unroll
                for (int nf2 = 0; nf2 < 2; nf2++) {
                    uint32_t wd = (bRow + nf2 * 16) * RSTRIDE + (k0 + bCol) * 2 + c * CHUNK;
                    ldsm4(wh[nf2], sb + OFF_WH + wd);
                    ldsm4(wl[nf2], sb + OFF_WL + wd);
                }
#pragma unroll
                for (int mf = 0; mf < 4; mf++)
#pragma unroll
                    for (int nf = 0; nf < 4; nf++) {
                        uint32_t* bh = &wh[nf >> 1][(nf & 1) * 2];
                        uint32_t* bl = &wl[nf >> 1][(nf & 1) * 2];
                        mma16816(acc[mf][nf], ah[mf], bh);
                        mma16816(acc[mf][nf], ah[mf], bl);
                        mma16816(acc[mf][nf], al[mf], bh);
                    }
            }
        }
        // epilogue
#pragma unroll
        for (int mf = 0; mf < 4; mf++) {
            int r0 = rbase + warpM * 64 + mf * 16 + (lane >> 2);
#pragma unroll
            for (int half = 0; half < 2; half++) {
                int row = r0 + half * 8;
                if (row >= NA) continue;
#pragma unroll
                for (int nf = 0; nf < 4; nf++) {
                    int col = warpN * 32 + nf * 8 + 2 * (lane & 3);
                    float v0 = acc[mf][nf][half * 2 + 0] + bias_s[col];
                    float v1 = acc[mf][nf][half * 2 + 1] + bias_s[col + 1];
                    if (RELU) { v0 = fmaxf(v0, 0.f); v1 = fmaxf(v1, 0.f); }
                    if (OUTBF) {
                        uint32_t h, l;
                        split2(v0, v1, h, l);
                        *(uint32_t*)(Ch + row * HID + col) = h;
                        *(uint32_t*)(Cl + row * HID + col) = l;
                    } else {
                        *(float2*)(Cf + row * HID + col) = make_float2(v0, v1);
                    }
                }
            }
        }
    };

    if (DB) {
        issue_tile(blockIdx.x * 128, OFF_A0H, OFF_A0L);
        int cur = 0;
        for (int t = blockIdx.x; t < NT; t += gridDim.x) {
            CP_WAIT0();
            __syncthreads();
            int next = t + gridDim.x;
            if (next < NT)
                issue_tile(next * 128, cur ? OFF_A0H : OFF_A1H, cur ? OFF_A0L : OFF_A1L);
            compute_store(t * 128, cur ? OFF_A1H : OFF_A0H, cur ? OFF_A1L : OFF_A0L);
            cur ^= 1;
        }
    } else {
        __syncthreads();
        for (int t = blockIdx.x; t < NT; t += gridDim.x) {
            int rbase = t * 128;
            for (int e = tid; e < KC * 2048; e += 256) {
                int c = e >> 11, q = e & 2047;
                int m = q >> 10;
                int r = (q >> 3) & 127, p = q & 7;
                int grow = rbase + r;
                const __nv_bfloat16* src = m ? Al : Ah;
                uint4 v = make_uint4(0, 0, 0, 0);
                if (grow < NA) v = *(const uint4*)(src + grow * K + c * 64 + p * 8);
                uint32_t off = (m ? OFF_A0L : OFF_A0H) + c * CHUNK + r * RSTRIDE + p * 16;
                if (m == 0) off = OFF_A0H + c * CHUNK + r * RSTRIDE + p * 16;
                else off = OFF_A0L + c * CHUNK + r * RSTRIDE + p * 16;
                *(uint4*)(smem + off) = v;
            }
            __syncthreads();
            compute_store(rbase, OFF_A0H, OFF_A0L);
            __syncthreads();
        }
    }
}

// ====================== BN stats ======================
__global__ void stats_kernel(int slot) {
    int col = threadIdx.x;
    float s = 0.f, q = 0.f;
    for (int r = blockIdx.x; r < NA; r += gridDim.x) {
        float v = g_agg[r * HID + col];
        s += v;
        q += v * v;
    }
    atomicAdd(&g_sumA[slot][col], s);
    atomicAdd(&g_sumsqA[slot][col], q);
}

// ====================== pooling (+fused BN/ReLU of last depth) =============
__global__ void pool_kernel(const int* __restrict__ seg, float* __restrict__ out,
                            const float* __restrict__ gamma,
                            const float* __restrict__ beta, int slot) {
    int m = blockIdx.x;
    int t = threadIdx.x;
    const float invN = 1.f / (float)NA;
    float mean = g_sumA[slot][t] * invN;
    float var = g_sumsqA[slot][t] * invN - mean * mean;
    float sc = gamma[t] * rsqrtf(var + 1e-5f);
    float sh = beta[t] - mean * sc;
    int lo = 0, hi = NA;
    while (lo < hi) { int mid = (lo + hi) >> 1; if (seg[mid] < m) lo = mid + 1; else hi = mid; }
    int start = lo;
    hi = NA;
    while (lo < hi) { int mid = (lo + hi) >> 1; if (seg[mid] < m + 1) lo = mid + 1; else hi = mid; }
    int end = lo;
    float s = 0.f;
    for (int a = start; a < end; a++)
        s += fmaxf(fmaf(g_agg[a * HID + t], sc, sh), 0.f);
    int cnt = end - start;
    out[m * HID + t] = (cnt > 0) ? s / (float)cnt : 0.f;
}

// ====================== launch ======================
extern "C" void kernel_launch(void* const* d_in, const int* in_sizes, int n_in,
                              void* d_out, int out_size) {
    const float* f_atoms = (const float*)d_in[0];
    const float* W_in    = (const float*)d_in[1];
    const float* b_in    = (const float*)d_in[2];
    const float* W1      = (const float*)d_in[3];
    const float* b1      = (const float*)d_in[4];
    const float* W2      = (const float*)d_in[5];
    const float* b2      = (const float*)d_in[6];
    const float* gamma   = (const float*)d_in[7];
    const float* beta    = (const float*)d_in[8];
    const float* epsp    = (const float*)d_in[9];
    const int*   ei      = (const int*)d_in[10];
    const int*   seg     = (const int*)d_in[11];
    float* out = (float*)d_out;

    float *p_x, *p_agg;
    __nv_bfloat16 *p_fh, *p_fl, *p_ah, *p_al, *p_hh, *p_hl;
    __nv_bfloat16 *p_wfh, *p_wfl, *p_w1h, *p_w1l, *p_w2h, *p_w2l;
    cudaGetSymbolAddress((void**)&p_x, g_x);
    cudaGetSymbolAddress((void**)&p_agg, g_agg);
    cudaGetSymbolAddress((void**)&p_fh, g_fh);
    cudaGetSymbolAddress((void**)&p_fl, g_fl);
    cudaGetSymbolAddress((void**)&p_ah, g_ah);
    cudaGetSymbolAddress((void**)&p_al, g_al);
    cudaGetSymbolAddress((void**)&p_hh, g_hh);
    cudaGetSymbolAddress((void**)&p_hl, g_hl);
    cudaGetSymbolAddress((void**)&p_wfh, g_wfh);
    cudaGetSymbolAddress((void**)&p_wfl, g_wfl);
    cudaGetSymbolAddress((void**)&p_w1h, g_w1h);
    cudaGetSymbolAddress((void**)&p_w1l, g_w1l);
    cudaGetSymbolAddress((void**)&p_w2h, g_w2h);
    cudaGetSymbolAddress((void**)&p_w2l, g_w2l);

    const int SMEM_SZ = 512 + 4 * 3 * CHUNK;  // 221696 (same for KC=3 single & KC=2 DB)
    cudaFuncSetAttribute(mma_gemm_kernel<3, false, true, false>,
                         cudaFuncAttributeMaxDynamicSharedMemorySize, SMEM_SZ);
    cudaFuncSetAttribute(mma_gemm_kernel<2, true, true, true>,
                         cudaFuncAttributeMaxDynamicSharedMemorySize, SMEM_SZ);
    cudaFuncSetAttribute(mma_gemm_kernel<2, true, false, false>,
                         cudaFuncAttributeMaxDynamicSharedMemorySize, SMEM_SZ);

    const int EDGE_BLOCKS = (NE + 255) / 256;

    // Launch order puts the input GEMM at slot 4 (the launch ncu profiles).
    prep_weights_kernel<<<96, 256>>>(W_in, W1, W2);
    convert_atoms_kernel<<<(NA * (KPAD / 2) + 255) / 256, 256>>>(f_atoms);
    zero_csr_kernel<<<98, 1024>>>();
    mma_gemm_kernel<3, false, true, false><<<148, 256, SMEM_SZ>>>(
        p_fh, p_fl, p_wfh, p_wfl, b_in, p_x, nullptr, nullptr);
    count_kernel<<<EDGE_BLOCKS, 256>>>(ei);
    scan_kernel<<<1, 1024>>>();
    fill_kernel<<<EDGE_BLOCKS, 256>>>(ei);

    for (int d = 0; d < 3; d++) {
        int rslot = (d + 1) & 1;       // stats slot of previous depth (d>=1)
        int zslot = d & 1;             // slot this depth's stats will use
        if (d == 0)
            gather_kernel<false><<<(NA + 7) / 8, 256>>>(p_x, epsp, d, nullptr, nullptr, 0, zslot);
        else
            gather_kernel<true><<<(NA + 7) / 8, 256>>>(p_agg, epsp, d,
                gamma + (d - 1) * HID, beta + (d - 1) * HID, rslot, zslot);
        mma_gemm_kernel<2, true, true, true><<<148, 256, SMEM_SZ>>>(
            p_ah, p_al, p_w1h + d * HID * HID, p_w1l + d * HID * HID,
            b1 + d * HID, nullptr, p_hh, p_hl);
        mma_gemm_kernel<2, true, false, false><<<148, 256, SMEM_SZ>>>(
            p_hh, p_hl, p_w2h + d * HID * HID, p_w2l + d * HID * HID,
            b2 + d * HID, p_agg, nullptr, nullptr);
        stats_kernel<<<256, 128>>>(d & 1);
    }

    pool_kernel<<<NM, HID>>>(seg, out, gamma + 2 * HID, beta + 2 * HID, 2 & 1);
}

// round 6
// speedup vs baseline: 1.5400x; 1.2858x over previous
#include <cuda_runtime.h>
#include <cuda_bf16.h>
#include <cstdint>

#define NA 50000
#define AFD 133
#define HID 128
#define NE 800000
#define NM 1024
#define KPAD 192
#define NT ((NA + 127) / 128)

#define RSTRIDE 144
#define CHUNK (128 * RSTRIDE)
#define GTHREADS 512

// ====================== helpers ======================
__device__ __forceinline__ uint32_t smem_u32(const void* p) {
    uint32_t a;
    asm("{ .reg .u64 t; cvta.to.shared.u64 t, %1; cvt.u32.u64 %0, t; }" : "=r"(a) : "l"(p));
    return a;
}
__device__ __forceinline__ void ldsm4(uint32_t* r, uint32_t addr) {
    asm volatile("ldmatrix.sync.aligned.m8n8.x4.shared.b16 {%0,%1,%2,%3}, [%4];"
                 : "=r"(r[0]), "=r"(r[1]), "=r"(r[2]), "=r"(r[3]) : "r"(addr));
}
__device__ __forceinline__ void mma16816(float* c, const uint32_t* a, const uint32_t* b) {
    asm volatile(
        "mma.sync.aligned.m16n8k16.row.col.f32.bf16.bf16.f32 "
        "{%0,%1,%2,%3}, {%4,%5,%6,%7}, {%8,%9}, {%0,%1,%2,%3};"
        : "+f"(c[0]), "+f"(c[1]), "+f"(c[2]), "+f"(c[3])
        : "r"(a[0]), "r"(a[1]), "r"(a[2]), "r"(a[3]), "r"(b[0]), "r"(b[1]));
}
__device__ __forceinline__ void cp_async16(uint32_t dst, const void* src, uint32_t bytes) {
    asm volatile("cp.async.cg.shared.global [%0], [%1], 16, %2;"
                 :: "r"(dst), "l"(src), "r"(bytes));
}
#define CP_COMMIT() asm volatile("cp.async.commit_group;" ::: "memory")
#define CP_WAIT0()  asm volatile("cp.async.wait_group 0;" ::: "memory")

__device__ __forceinline__ void split2(float v0, float v1, uint32_t& h, uint32_t& l) {
    __nv_bfloat16 h0 = __float2bfloat16(v0), h1 = __float2bfloat16(v1);
    __nv_bfloat16 l0 = __float2bfloat16(v0 - __bfloat162float(h0));
    __nv_bfloat16 l1 = __float2bfloat16(v1 - __bfloat162float(h1));
    h = ((uint32_t)__bfloat16_as_ushort(h1) << 16) | __bfloat16_as_ushort(h0);
    l = ((uint32_t)__bfloat16_as_ushort(l1) << 16) | __bfloat16_as_ushort(l0);
}

// ====================== scratch ======================
__device__ float g_x[NA * HID];
__device__ float g_agg[NA * HID];
__device__ __nv_bfloat16 g_fh[NA * KPAD], g_fl[NA * KPAD];
__device__ __nv_bfloat16 g_ah[NA * HID], g_al[NA * HID];
__device__ __nv_bfloat16 g_hh[NA * HID], g_hl[NA * HID];
__device__ __nv_bfloat16 g_wfh[HID * KPAD], g_wfl[HID * KPAD];
__device__ __nv_bfloat16 g_w1h[3 * HID * HID], g_w1l[3 * HID * HID];
__device__ __nv_bfloat16 g_w2h[3 * HID * HID], g_w2l[3 * HID * HID];
__device__ int g_deg[NA];
__device__ int g_off[NA + 1];
__device__ int g_pos[NA];
__device__ int g_srclist[NE];
__device__ float g_sumA[2][HID];
__device__ float g_sumsqA[2][HID];

// ====================== conversions ======================
__global__ void convert_atoms_kernel(const float* __restrict__ f) {
    int i = blockIdx.x * blockDim.x + threadIdx.x;
    int total = NA * (KPAD / 2);
    if (i >= total) return;
    int row = i / (KPAD / 2), p = i % (KPAD / 2);
    int k = 2 * p;
    float v0 = (k < AFD) ? f[row * AFD + k] : 0.f;
    float v1 = (k + 1 < AFD) ? f[row * AFD + k + 1] : 0.f;
    uint32_t h, l;
    split2(v0, v1, h, l);
    ((uint32_t*)g_fh)[row * (KPAD / 2) + p] = h;
    ((uint32_t*)g_fl)[row * (KPAD / 2) + p] = l;
}

__global__ void prep_weights_kernel(const float* __restrict__ W_in,
                                    const float* __restrict__ W1,
                                    const float* __restrict__ W2) {
    int i = blockIdx.x * blockDim.x + threadIdx.x;
    int stride = gridDim.x * blockDim.x;
    for (int idx = i; idx < HID * KPAD; idx += stride) {
        int n = idx / KPAD, k = idx % KPAD;
        float v = (k < AFD) ? W_in[k * HID + n] : 0.f;
        __nv_bfloat16 h = __float2bfloat16(v);
        g_wfh[idx] = h;
        g_wfl[idx] = __float2bfloat16(v - __bfloat162float(h));
    }
    for (int idx = i; idx < 3 * HID * HID; idx += stride) {
        int d = idx / (HID * HID);
        int r = idx % (HID * HID);
        int n = r / HID, k = r % HID;
        float v1 = W1[d * HID * HID + k * HID + n];
        float v2 = W2[d * HID * HID + k * HID + n];
        __nv_bfloat16 h1 = __float2bfloat16(v1);
        g_w1h[idx] = h1;
        g_w1l[idx] = __float2bfloat16(v1 - __bfloat162float(h1));
        __nv_bfloat16 h2 = __float2bfloat16(v2);
        g_w2h[idx] = h2;
        g_w2l[idx] = __float2bfloat16(v2 - __bfloat162float(h2));
    }
}

// ====================== CSR build ======================
__global__ void zero_csr_kernel() {
    int i = blockIdx.x * blockDim.x + threadIdx.x;
    int stride = gridDim.x * blockDim.x;
    for (int k = i; k < NA; k += stride) { g_deg[k] = 0; g_pos[k] = 0; }
}
__global__ void count_kernel(const int* __restrict__ ei) {
    int e = blockIdx.x * blockDim.x + threadIdx.x;
    if (e < NE) atomicAdd(&g_deg[ei[NE + e]], 1);
}
__global__ void scan_kernel() {
    __shared__ int sm[1024];
    int t = threadIdx.x;
    const int C = (NA + 1023) / 1024;
    int start = t * C;
    int end = min((t + 1) * C, NA);
    int s = 0;
    for (int i = start; i < end; i++) s += g_deg[i];
    sm[t] = s;
    __syncthreads();
    for (int d = 1; d < 1024; d <<= 1) {
        int v = (t >= d) ? sm[t - d] : 0;
        __syncthreads();
        sm[t] += v;
        __syncthreads();
    }
    int run = (t > 0) ? sm[t - 1] : 0;
    for (int i = start; i < end; i++) { g_off[i] = run; run += g_deg[i]; }
    if (start < NA && end == NA) g_off[NA] = run;
}
__global__ void fill_kernel(const int* __restrict__ ei) {
    int e = blockIdx.x * blockDim.x + threadIdx.x;
    if (e < NE) {
        int tgt = ei[NE + e];
        int src = ei[e];
        int slot = atomicAdd(&g_pos[tgt], 1);
        g_srclist[g_off[tgt] + slot] = src;
    }
}

// ====================== gather (+fused BN/ReLU of previous depth) ==========
template <bool BN>
__global__ void gather_kernel(const float* __restrict__ src_arr,
                              const float* __restrict__ epsp, int d,
                              const float* __restrict__ gamma,
                              const float* __restrict__ beta,
                              int rslot, int zslot) {
    if (blockIdx.x == 0 && threadIdx.x < 2 * HID) {
        if (threadIdx.x < HID) g_sumA[zslot][threadIdx.x] = 0.f;
        else g_sumsqA[zslot][threadIdx.x - HID] = 0.f;
    }
    int gw = (blockIdx.x * blockDim.x + threadIdx.x) >> 5;
    int lane = threadIdx.x & 31;
    if (gw >= NA) return;

    float4 bsc = make_float4(0.f, 0.f, 0.f, 0.f), bsh = make_float4(0.f, 0.f, 0.f, 0.f);
    if (BN) {
        const float invN = 1.f / (float)NA;
        int c0 = lane * 4;
#pragma unroll
        for (int q = 0; q < 4; q++) {
            int c = c0 + q;
            float mean = g_sumA[rslot][c] * invN;
            float var = g_sumsqA[rslot][c] * invN - mean * mean;
            float sc = gamma[c] * rsqrtf(var + 1e-5f);
            float sh = beta[c] - mean * sc;
            ((float*)&bsc)[q] = sc;
            ((float*)&bsh)[q] = sh;
        }
    }
    float scale = 1.f + epsp[d];
    const float4* x4 = (const float4*)src_arr;

    auto loadrow = [&](int r) -> float4 {
        float4 v = x4[r * 32 + lane];
        if (BN) {
            v.x = fmaxf(fmaf(v.x, bsc.x, bsh.x), 0.f);
            v.y = fmaxf(fmaf(v.y, bsc.y, bsh.y), 0.f);
            v.z = fmaxf(fmaf(v.z, bsc.z, bsh.z), 0.f);
            v.w = fmaxf(fmaf(v.w, bsc.w, bsh.w), 0.f);
        }
        return v;
    };

    float4 acc = loadrow(gw);
    acc.x *= scale; acc.y *= scale; acc.z *= scale; acc.w *= scale;
    int j = g_off[gw];
    int e = g_off[gw + 1];
    for (; j + 4 <= e; j += 4) {
        int s0 = g_srclist[j], s1 = g_srclist[j + 1];
        int s2 = g_srclist[j + 2], s3 = g_srclist[j + 3];
        float4 v0 = loadrow(s0), v1 = loadrow(s1), v2 = loadrow(s2), v3 = loadrow(s3);
        acc.x += (v0.x + v1.x) + (v2.x + v3.x);
        acc.y += (v0.y + v1.y) + (v2.y + v3.y);
        acc.z += (v0.z + v1.z) + (v2.z + v3.z);
        acc.w += (v0.w + v1.w) + (v2.w + v3.w);
    }
    for (; j < e; j++) {
        float4 v = loadrow(g_srclist[j]);
        acc.x += v.x; acc.y += v.y; acc.z += v.z; acc.w += v.w;
    }
    uint32_t h01, l01, h23, l23;
    split2(acc.x, acc.y, h01, l01);
    split2(acc.z, acc.w, h23, l23);
    ((uint2*)g_ah)[gw * 32 + lane] = make_uint2(h01, h23);
    ((uint2*)g_al)[gw * 32 + lane] = make_uint2(l01, l23);
}

// ====================== bf16x3 mma.sync GEMM (512 thr, 16 warps) ===========
// CTA tile 128x128, warp tile 32x32 (4M x 4N warps).
template <int KC, bool DB, bool RELU, bool OUTBF, bool STATS>
__global__ __launch_bounds__(GTHREADS, 1) void mma_gemm_kernel(
    const __nv_bfloat16* __restrict__ Ah, const __nv_bfloat16* __restrict__ Al,
    const __nv_bfloat16* __restrict__ Wh, const __nv_bfloat16* __restrict__ Wl,
    const float* __restrict__ bias,
    float* __restrict__ Cf, __nv_bfloat16* __restrict__ Ch, __nv_bfloat16* __restrict__ Cl,
    int slot) {
    extern __shared__ char smem[];
    const int K = KC * 64;
    const uint32_t OFF_WH = 512;
    const uint32_t OFF_WL = OFF_WH + KC * CHUNK;
    const uint32_t OFF_A0H = OFF_WL + KC * CHUNK;
    const uint32_t OFF_A0L = OFF_A0H + KC * CHUNK;
    const uint32_t OFF_A1H = OFF_A0L + KC * CHUNK;  // DB only
    const uint32_t OFF_A1L = OFF_A1H + KC * CHUNK;  // DB only
    const uint32_t sb = smem_u32(smem);

    int tid = threadIdx.x;
    int wid = tid >> 5, lane = tid & 31;
    int warpM = wid & 3, warpN = wid >> 2;

    float* bias_s = (float*)smem;
    if (tid < HID) bias_s[tid] = bias[tid];

    // W hi/lo resident
    for (int e = tid; e < KC * 2048; e += GTHREADS) {
        int c = e >> 11, q = e & 2047;
        int m = q >> 10;
        int r = (q >> 3) & 127, p = q & 7;
        const __nv_bfloat16* src = m ? Wl : Wh;
        uint4 v = *(const uint4*)(src + r * K + c * 64 + p * 8);
        uint32_t off = (m ? OFF_WL : OFF_WH) + c * CHUNK + r * RSTRIDE + p * 16;
        *(uint4*)(smem + off) = v;
    }

    int aRow = warpM * 32 + (lane & 15);
    int aCol = (lane >> 4) * 8;
    int bRow = warpN * 32 + ((lane >> 4) * 8) + (lane & 7);
    int bCol = ((lane >> 3) & 1) * 8;

    float colSum[8], colSq[8];
    if (STATS) {
#pragma unroll
        for (int j = 0; j < 8; j++) { colSum[j] = 0.f; colSq[j] = 0.f; }
    }

    auto issue_tile = [&](int rbase, uint32_t offAH, uint32_t offAL) {
#pragma unroll
        for (int e = tid; e < KC * 2048; e += GTHREADS) {
            int c = e >> 11, q = e & 2047;
            int m = q >> 10;
            int r = (q >> 3) & 127, p = q & 7;
            int grow = rbase + r;
            const __nv_bfloat16* src = m ? Al : Ah;
            int sg = grow < NA ? grow : NA - 1;
            uint32_t bytes = grow < NA ? 16u : 0u;
            uint32_t off = (m ? offAL : offAH) + c * CHUNK + r * RSTRIDE + p * 16;
            cp_async16(sb + off, src + sg * K + c * 64 + p * 8, bytes);
        }
        CP_COMMIT();
    };

    auto compute_store = [&](int rbase, uint32_t offAH, uint32_t offAL) {
        float acc[2][4][4];
#pragma unroll
        for (int mf = 0; mf < 2; mf++)
#pragma unroll
            for (int nf = 0; nf < 4; nf++)
#pragma unroll
                for (int r = 0; r < 4; r++) acc[mf][nf][r] = 0.f;
#pragma unroll
        for (int c = 0; c < KC; c++) {
#pragma unroll
            for (int kk = 0; kk < 4; kk++) {
                int k0 = kk * 16;
                uint32_t ah[2][4], al[2][4], wh[2][4], wl[2][4];
#pragma unroll
                for (int mf = 0; mf < 2; mf++) {
                    uint32_t ad = (aRow + mf * 16) * RSTRIDE + (k0 + aCol) * 2 + c * CHUNK;
                    ldsm4(ah[mf], sb + offAH + ad);
                    ldsm4(al[mf], sb + offAL + ad);
                }
#pragma unroll
                for (int nf2 = 0; nf2 < 2; nf2++) {
                    uint32_t wd = (bRow + nf2 * 16) * RSTRIDE + (k0 + bCol) * 2 + c * CHUNK;
                    ldsm4(wh[nf2], sb + OFF_WH + wd);
                    ldsm4(wl[nf2], sb + OFF_WL + wd);
                }
#pragma unroll
                for (int mf = 0; mf < 2; mf++)
#pragma unroll
                    for (int nf = 0; nf < 4; nf++) {
                        uint32_t* bh = &wh[nf >> 1][(nf & 1) * 2];
                        uint32_t* bl = &wl[nf >> 1][(nf & 1) * 2];
                        mma16816(acc[mf][nf], ah[mf], bh);
                        mma16816(acc[mf][nf], ah[mf], bl);
                        mma16816(acc[mf][nf], al[mf], bh);
                    }
            }
        }
#pragma unroll
        for (int mf = 0; mf < 2; mf++) {
            int r0 = rbase + warpM * 32 + mf * 16 + (lane >> 2);
#pragma unroll
            for (int half = 0; half < 2; half++) {
                int row = r0 + half * 8;
                if (row >= NA) continue;
#pragma unroll
                for (int nf = 0; nf < 4; nf++) {
                    int col = warpN * 32 + nf * 8 + 2 * (lane & 3);
                    float v0 = acc[mf][nf][half * 2 + 0] + bias_s[col];
                    float v1 = acc[mf][nf][half * 2 + 1] + bias_s[col + 1];
                    if (RELU) { v0 = fmaxf(v0, 0.f); v1 = fmaxf(v1, 0.f); }
                    if (STATS) {
                        colSum[nf * 2] += v0; colSq[nf * 2] += v0 * v0;
                        colSum[nf * 2 + 1] += v1; colSq[nf * 2 + 1] += v1 * v1;
                    }
                    if (OUTBF) {
                        uint32_t h, l;
                        split2(v0, v1, h, l);
                        *(uint32_t*)(Ch + row * HID + col) = h;
                        *(uint32_t*)(Cl + row * HID + col) = l;
                    } else {
                        *(float2*)(Cf + row * HID + col) = make_float2(v0, v1);
                    }
                }
            }
        }
    };

    if (DB) {
        issue_tile(blockIdx.x * 128, OFF_A0H, OFF_A0L);
        int cur = 0;
        for (int t = blockIdx.x; t < NT; t += gridDim.x) {
            CP_WAIT0();
            __syncthreads();
            int next = t + gridDim.x;
            if (next < NT)
                issue_tile(next * 128, cur ? OFF_A0H : OFF_A1H, cur ? OFF_A0L : OFF_A1L);
            compute_store(t * 128, cur ? OFF_A1H : OFF_A0H, cur ? OFF_A1L : OFF_A0L);
            cur ^= 1;
        }
    } else {
        __syncthreads();
        for (int t = blockIdx.x; t < NT; t += gridDim.x) {
            int rbase = t * 128;
            for (int e = tid; e < KC * 2048; e += GTHREADS) {
                int c = e >> 11, q = e & 2047;
                int m = q >> 10;
                int r = (q >> 3) & 127, p = q & 7;
                int grow = rbase + r;
                const __nv_bfloat16* src = m ? Al : Ah;
                uint4 v = make_uint4(0, 0, 0, 0);
                if (grow < NA) v = *(const uint4*)(src + grow * K + c * 64 + p * 8);
                uint32_t off = (m ? OFF_A0L : OFF_A0H) + c * CHUNK + r * RSTRIDE + p * 16;
                *(uint4*)(smem + off) = v;
            }
            __syncthreads();
            compute_store(rbase, OFF_A0H, OFF_A0L);
            __syncthreads();
        }
    }

    if (STATS) {
        // reduce colSum/colSq -> smem -> global atomics
        __syncthreads();
        float* rs = (float*)(smem + 512);  // 256 floats (clobbers W area; done computing)
        if (tid < 256) rs[tid] = 0.f;
        __syncthreads();
#pragma unroll
        for (int j = 0; j < 8; j++) {
            int col = warpN * 32 + ((j >> 1) /*nf*/) * 8 + 2 * (lane & 3) + (j & 1);
            // recompute col from j: j = nf*2 + parity
            atomicAdd(&rs[col], colSum[j]);
            atomicAdd(&rs[128 + col], colSq[j]);
        }
        __syncthreads();
        if (tid < 128) {
            atomicAdd(&g_sumA[slot][tid], rs[tid]);
            atomicAdd(&g_sumsqA[slot][tid], rs[128 + tid]);
        }
    }
}

// ====================== pooling (+fused BN/ReLU of last depth) =============
__global__ void pool_kernel(const int* __restrict__ seg, float* __restrict__ out,
                            const float* __restrict__ gamma,
                            const float* __restrict__ beta, int slot) {
    int m = blockIdx.x;
    int t = threadIdx.x;
    const float invN = 1.f / (float)NA;
    float mean = g_sumA[slot][t] * invN;
    float var = g_sumsqA[slot][t] * invN - mean * mean;
    float sc = gamma[t] * rsqrtf(var + 1e-5f);
    float sh = beta[t] - mean * sc;
    int lo = 0, hi = NA;
    while (lo < hi) { int mid = (lo + hi) >> 1; if (seg[mid] < m) lo = mid + 1; else hi = mid; }
    int start = lo;
    hi = NA;
    while (lo < hi) { int mid = (lo + hi) >> 1; if (seg[mid] < m + 1) lo = mid + 1; else hi = mid; }
    int end = lo;
    float s = 0.f;
    for (int a = start; a < end; a++)
        s += fmaxf(fmaf(g_agg[a * HID + t], sc, sh), 0.f);
    int cnt = end - start;
    out[m * HID + t] = (cnt > 0) ? s / (float)cnt : 0.f;
}

// ====================== launch ======================
extern "C" void kernel_launch(void* const* d_in, const int* in_sizes, int n_in,
                              void* d_out, int out_size) {
    const float* f_atoms = (const float*)d_in[0];
    const float* W_in    = (const float*)d_in[1];
    const float* b_in    = (const float*)d_in[2];
    const float* W1      = (const float*)d_in[3];
    const float* b1      = (const float*)d_in[4];
    const float* W2      = (const float*)d_in[5];
    const float* b2      = (const float*)d_in[6];
    const float* gamma   = (const float*)d_in[7];
    const float* beta    = (const float*)d_in[8];
    const float* epsp    = (const float*)d_in[9];
    const int*   ei      = (const int*)d_in[10];
    const int*   seg     = (const int*)d_in[11];
    float* out = (float*)d_out;

    float *p_x, *p_agg;
    __nv_bfloat16 *p_fh, *p_fl, *p_ah, *p_al, *p_hh, *p_hl;
    __nv_bfloat16 *p_wfh, *p_wfl, *p_w1h, *p_w1l, *p_w2h, *p_w2l;
    cudaGetSymbolAddress((void**)&p_x, g_x);
    cudaGetSymbolAddress((void**)&p_agg, g_agg);
    cudaGetSymbolAddress((void**)&p_fh, g_fh);
    cudaGetSymbolAddress((void**)&p_fl, g_fl);
    cudaGetSymbolAddress((void**)&p_ah, g_ah);
    cudaGetSymbolAddress((void**)&p_al, g_al);
    cudaGetSymbolAddress((void**)&p_hh, g_hh);
    cudaGetSymbolAddress((void**)&p_hl, g_hl);
    cudaGetSymbolAddress((void**)&p_wfh, g_wfh);
    cudaGetSymbolAddress((void**)&p_wfl, g_wfl);
    cudaGetSymbolAddress((void**)&p_w1h, g_w1h);
    cudaGetSymbolAddress((void**)&p_w1l, g_w1l);
    cudaGetSymbolAddress((void**)&p_w2h, g_w2h);
    cudaGetSymbolAddress((void**)&p_w2l, g_w2l);

    const int SMEM_SZ = 512 + 4 * 3 * CHUNK;  // 221696
    cudaFuncSetAttribute(mma_gemm_kernel<3, false, true, false, false>,
                         cudaFuncAttributeMaxDynamicSharedMemorySize, SMEM_SZ);
    cudaFuncSetAttribute(mma_gemm_kernel<2, true, true, true, false>,
                         cudaFuncAttributeMaxDynamicSharedMemorySize, SMEM_SZ);
    cudaFuncSetAttribute(mma_gemm_kernel<2, true, false, false, true>,
                         cudaFuncAttributeMaxDynamicSharedMemorySize, SMEM_SZ);

    const int EDGE_BLOCKS = (NE + 255) / 256;

    prep_weights_kernel<<<96, 256>>>(W_in, W1, W2);
    convert_atoms_kernel<<<(NA * (KPAD / 2) + 255) / 256, 256>>>(f_atoms);
    zero_csr_kernel<<<98, 1024>>>();
    mma_gemm_kernel<3, false, true, false, false><<<148, GTHREADS, SMEM_SZ>>>(
        p_fh, p_fl, p_wfh, p_wfl, b_in, p_x, nullptr, nullptr, 0);
    count_kernel<<<EDGE_BLOCKS, 256>>>(ei);
    scan_kernel<<<1, 1024>>>();
    fill_kernel<<<EDGE_BLOCKS, 256>>>(ei);

    for (int d = 0; d < 3; d++) {
        int rslot = (d + 1) & 1;   // previous depth's stats
        int zslot = d & 1;         // this depth's stats slot (gemm2 accumulates)
        if (d == 0)
            gather_kernel<false><<<(NA + 7) / 8, 256>>>(p_x, epsp, d, nullptr, nullptr, 0, zslot);
        else
            gather_kernel<true><<<(NA + 7) / 8, 256>>>(p_agg, epsp, d,
                gamma + (d - 1) * HID, beta + (d - 1) * HID, rslot, zslot);
        mma_gemm_kernel<2, true, true, true, false><<<148, GTHREADS, SMEM_SZ>>>(
            p_ah, p_al, p_w1h + d * HID * HID, p_w1l + d * HID * HID,
            b1 + d * HID, nullptr, p_hh, p_hl, 0);
        mma_gemm_kernel<2, true, false, false, true><<<148, GTHREADS, SMEM_SZ>>>(
            p_hh, p_hl, p_w2h + d * HID * HID, p_w2l + d * HID * HID,
            b2 + d * HID, p_agg, nullptr, nullptr, zslot);
    }

    pool_kernel<<<NM, HID>>>(seg, out, gamma + 2 * HID, beta + 2 * HID, 0);
}

// round 9
// speedup vs baseline: 1.6383x; 1.0639x over previous
#include <cuda_runtime.h>
#include <cuda_bf16.h>
#include <cstdint>

#define NA 50000
#define AFD 133
#define HID 128
#define NE 800000
#define NM 1024
#define KPAD 192
#define NT64 ((NA + 63) / 64)   // 782

#define RSTRIDE 144
#define WCHUNK 18432            // 128 rows * 144
#define C64 9216                // 64 rows * 144
#define GTHREADS 512

// ====================== helpers ======================
__device__ __forceinline__ uint32_t smem_u32(const void* p) {
    uint32_t a;
    asm("{ .reg .u64 t; cvta.to.shared.u64 t, %1; cvt.u32.u64 %0, t; }" : "=r"(a) : "l"(p));
    return a;
}
__device__ __forceinline__ void ldsm4(uint32_t* r, uint32_t addr) {
    asm volatile("ldmatrix.sync.aligned.m8n8.x4.shared.b16 {%0,%1,%2,%3}, [%4];"
                 : "=r"(r[0]), "=r"(r[1]), "=r"(r[2]), "=r"(r[3]) : "r"(addr));
}
__device__ __forceinline__ void mma16816(float* c, const uint32_t* a, const uint32_t* b) {
    asm volatile(
        "mma.sync.aligned.m16n8k16.row.col.f32.bf16.bf16.f32 "
        "{%0,%1,%2,%3}, {%4,%5,%6,%7}, {%8,%9}, {%0,%1,%2,%3};"
        : "+f"(c[0]), "+f"(c[1]), "+f"(c[2]), "+f"(c[3])
        : "r"(a[0]), "r"(a[1]), "r"(a[2]), "r"(a[3]), "r"(b[0]), "r"(b[1]));
}
__device__ __forceinline__ void cp_async16(uint32_t dst, const void* src, uint32_t bytes) {
    asm volatile("cp.async.cg.shared.global [%0], [%1], 16, %2;"
                 :: "r"(dst), "l"(src), "r"(bytes));
}
#define CP_COMMIT() asm volatile("cp.async.commit_group;" ::: "memory")
#define CP_WAIT0()  asm volatile("cp.async.wait_group 0;" ::: "memory")

__device__ __forceinline__ void split2(float v0, float v1, uint32_t& h, uint32_t& l) {
    __nv_bfloat16 h0 = __float2bfloat16(v0), h1 = __float2bfloat16(v1);
    __nv_bfloat16 l0 = __float2bfloat16(v0 - __bfloat162float(h0));
    __nv_bfloat16 l1 = __float2bfloat16(v1 - __bfloat162float(h1));
    h = ((uint32_t)__bfloat16_as_ushort(h1) << 16) | __bfloat16_as_ushort(h0);
    l = ((uint32_t)__bfloat16_as_ushort(l1) << 16) | __bfloat16_as_ushort(l0);
}

// ====================== scratch ======================
__device__ float g_x[NA * HID];
__device__ float g_agg[NA * HID];
__device__ __nv_bfloat16 g_fh[NA * KPAD], g_fl[NA * KPAD];
__device__ __nv_bfloat16 g_ah[NA * HID], g_al[NA * HID];
__device__ __nv_bfloat16 g_wfh[HID * KPAD], g_wfl[HID * KPAD];
__device__ __nv_bfloat16 g_w1h[3 * HID * HID], g_w1l[3 * HID * HID];
__device__ __nv_bfloat16 g_w2h[3 * HID * HID], g_w2l[3 * HID * HID];
__device__ int g_deg[NA];
__device__ int g_off[NA + 1];
__device__ int g_pos[NA];
__device__ int g_srclist[NE];
__device__ float g_sumA[2][HID];
__device__ float g_sumsqA[2][HID];

// ====================== conversions ======================
__global__ void convert_atoms_kernel(const float* __restrict__ f) {
    int i = blockIdx.x * blockDim.x + threadIdx.x;
    int total = NA * (KPAD / 2);
    if (i >= total) return;
    int row = i / (KPAD / 2), p = i % (KPAD / 2);
    int k = 2 * p;
    float v0 = (k < AFD) ? f[row * AFD + k] : 0.f;
    float v1 = (k + 1 < AFD) ? f[row * AFD + k + 1] : 0.f;
    uint32_t h, l;
    split2(v0, v1, h, l);
    ((uint32_t*)g_fh)[row * (KPAD / 2) + p] = h;
    ((uint32_t*)g_fl)[row * (KPAD / 2) + p] = l;
}

__global__ void prep_weights_kernel(const float* __restrict__ W_in,
                                    const float* __restrict__ W1,
                                    const float* __restrict__ W2) {
    int i = blockIdx.x * blockDim.x + threadIdx.x;
    int stride = gridDim.x * blockDim.x;
    for (int idx = i; idx < HID * KPAD; idx += stride) {
        int n = idx / KPAD, k = idx % KPAD;
        float v = (k < AFD) ? W_in[k * HID + n] : 0.f;
        __nv_bfloat16 h = __float2bfloat16(v);
        g_wfh[idx] = h;
        g_wfl[idx] = __float2bfloat16(v - __bfloat162float(h));
    }
    for (int idx = i; idx < 3 * HID * HID; idx += stride) {
        int d = idx / (HID * HID);
        int r = idx % (HID * HID);
        int n = r / HID, k = r % HID;
        float v1 = W1[d * HID * HID + k * HID + n];
        float v2 = W2[d * HID * HID + k * HID + n];
        __nv_bfloat16 h1 = __float2bfloat16(v1);
        g_w1h[idx] = h1;
        g_w1l[idx] = __float2bfloat16(v1 - __bfloat162float(h1));
        __nv_bfloat16 h2 = __float2bfloat16(v2);
        g_w2h[idx] = h2;
        g_w2l[idx] = __float2bfloat16(v2 - __bfloat162float(h2));
    }
}

// ====================== CSR build ======================
__global__ void zero_csr_kernel() {
    int i = blockIdx.x * blockDim.x + threadIdx.x;
    int stride = gridDim.x * blockDim.x;
    for (int k = i; k < NA; k += stride) { g_deg[k] = 0; g_pos[k] = 0; }
}
__global__ void count_kernel(const int* __restrict__ ei) {
    int e = blockIdx.x * blockDim.x + threadIdx.x;
    if (e < NE) atomicAdd(&g_deg[ei[NE + e]], 1);
}
__global__ void scan_kernel() {
    __shared__ int sm[1024];
    int t = threadIdx.x;
    const int C = (NA + 1023) / 1024;
    int start = t * C;
    int end = min((t + 1) * C, NA);
    int s = 0;
    for (int i = start; i < end; i++) s += g_deg[i];
    sm[t] = s;
    __syncthreads();
    for (int d = 1; d < 1024; d <<= 1) {
        int v = (t >= d) ? sm[t - d] : 0;
        __syncthreads();
        sm[t] += v;
        __syncthreads();
    }
    int run = (t > 0) ? sm[t - 1] : 0;
    for (int i = start; i < end; i++) { g_off[i] = run; run += g_deg[i]; }
    if (start < NA && end == NA) g_off[NA] = run;
}
__global__ void fill_kernel(const int* __restrict__ ei) {
    int e = blockIdx.x * blockDim.x + threadIdx.x;
    if (e < NE) {
        int tgt = ei[NE + e];
        int src = ei[e];
        int slot = atomicAdd(&g_pos[tgt], 1);
        g_srclist[g_off[tgt] + slot] = src;
    }
}

// ====================== gather (+fused BN/ReLU of previous depth) ==========
template <bool BN>
__global__ void gather_kernel(const float* __restrict__ src_arr,
                              const float* __restrict__ epsp, int d,
                              const float* __restrict__ gamma,
                              const float* __restrict__ beta,
                              int rslot, int zslot) {
    if (blockIdx.x == 0 && threadIdx.x < 2 * HID) {
        if (threadIdx.x < HID) g_sumA[zslot][threadIdx.x] = 0.f;
        else g_sumsqA[zslot][threadIdx.x - HID] = 0.f;
    }
    int gw = (blockIdx.x * blockDim.x + threadIdx.x) >> 5;
    int lane = threadIdx.x & 31;
    if (gw >= NA) return;

    float4 bsc = make_float4(0.f, 0.f, 0.f, 0.f), bsh = make_float4(0.f, 0.f, 0.f, 0.f);
    if (BN) {
        const float invN = 1.f / (float)NA;
        int c0 = lane * 4;
#pragma unroll
        for (int q = 0; q < 4; q++) {
            int c = c0 + q;
            float mean = g_sumA[rslot][c] * invN;
            float var = g_sumsqA[rslot][c] * invN - mean * mean;
            float sc = gamma[c] * rsqrtf(var + 1e-5f);
            float sh = beta[c] - mean * sc;
            ((float*)&bsc)[q] = sc;
            ((float*)&bsh)[q] = sh;
        }
    }
    float scale = 1.f + epsp[d];
    const float4* x4 = (const float4*)src_arr;

    auto loadrow = [&](int r) -> float4 {
        float4 v = x4[r * 32 + lane];
        if (BN) {
            v.x = fmaxf(fmaf(v.x, bsc.x, bsh.x), 0.f);
            v.y = fmaxf(fmaf(v.y, bsc.y, bsh.y), 0.f);
            v.z = fmaxf(fmaf(v.z, bsc.z, bsh.z), 0.f);
            v.w = fmaxf(fmaf(v.w, bsc.w, bsh.w), 0.f);
        }
        return v;
    };

    float4 acc = loadrow(gw);
    acc.x *= scale; acc.y *= scale; acc.z *= scale; acc.w *= scale;
    int j = g_off[gw];
    int e = g_off[gw + 1];
    for (; j + 4 <= e; j += 4) {
        int s0 = g_srclist[j], s1 = g_srclist[j + 1];
        int s2 = g_srclist[j + 2], s3 = g_srclist[j + 3];
        float4 v0 = loadrow(s0), v1 = loadrow(s1), v2 = loadrow(s2), v3 = loadrow(s3);
        acc.x += (v0.x + v1.x) + (v2.x + v3.x);
        acc.y += (v0.y + v1.y) + (v2.y + v3.y);
        acc.z += (v0.z + v1.z) + (v2.z + v3.z);
        acc.w += (v0.w + v1.w) + (v2.w + v3.w);
    }
    for (; j < e; j++) {
        float4 v = loadrow(g_srclist[j]);
        acc.x += v.x; acc.y += v.y; acc.z += v.z; acc.w += v.w;
    }
    uint32_t h01, l01, h23, l23;
    split2(acc.x, acc.y, h01, l01);
    split2(acc.z, acc.w, h23, l23);
    ((uint2*)g_ah)[gw * 32 + lane] = make_uint2(h01, h23);
    ((uint2*)g_al)[gw * 32 + lane] = make_uint2(l01, l23);
}

// ====================== input GEMM (KC=3, 64-row tiles, DB) ================
// x = relu(f @ W_in + b_in), bf16x3. 512 thr, warp tile 16x32.
__global__ __launch_bounds__(GTHREADS, 1) void gemm_in_kernel(
    const __nv_bfloat16* __restrict__ Ah, const __nv_bfloat16* __restrict__ Al,
    const __nv_bfloat16* __restrict__ Wh, const __nv_bfloat16* __restrict__ Wl,
    const float* __restrict__ bias, float* __restrict__ Cf) {
    extern __shared__ char smem[];
    const int K = 192;
    const uint32_t OFF_WH = 512;
    const uint32_t OFF_WL = 512 + 3 * WCHUNK;        // 55808
    const uint32_t OFF_A = 512 + 6 * WCHUNK;         // 111104
    // buf b (0/1), part m (0=h,1=l): OFF_A + b*55296 + m*27648
    const uint32_t sb = smem_u32(smem);
    int tid = threadIdx.x;
    int wid = tid >> 5, lane = tid & 31;
    int warpM = wid & 3, warpN = wid >> 2;

    float* bias_s = (float*)smem;
    if (tid < HID) bias_s[tid] = bias[tid];

    // W resident (128-row chunks, KC=3)
    for (int e = tid; e < 6144; e += GTHREADS) {
        int m = e / 3072, q = e % 3072;
        int c = q >> 10, r = (q >> 3) & 127, p = q & 7;
        const __nv_bfloat16* src = m ? Wl : Wh;
        uint4 v = *(const uint4*)(src + r * K + c * 64 + p * 8);
        *(uint4*)(smem + (m ? OFF_WL : OFF_WH) + c * WCHUNK + r * RSTRIDE + p * 16) = v;
    }

    int aRow = warpM * 16 + (lane & 15);
    int aCol = (lane >> 4) * 8;
    int bRow = warpN * 32 + ((lane >> 4) * 8) + (lane & 7);
    int bCol = ((lane >> 3) & 1) * 8;

    auto issue_tile = [&](int row0, int buf) {
#pragma unroll
        for (int e = tid; e < 3072; e += GTHREADS) {
            int m = e / 1536, q = e % 1536;
            int c = q >> 9, r = (q >> 3) & 63, p = q & 7;
            int grow = row0 + r;
            const __nv_bfloat16* src = m ? Al : Ah;
            int sg = grow < NA ? grow : NA - 1;
            uint32_t bytes = grow < NA ? 16u : 0u;
            uint32_t off = OFF_A + buf * 55296 + m * 27648 + c * C64 + r * RSTRIDE + p * 16;
            cp_async16(sb + off, src + sg * K + c * 64 + p * 8, bytes);
        }
        CP_COMMIT();
    };

    issue_tile(blockIdx.x * 64, 0);
    int cur = 0;
    for (int t = blockIdx.x; t < NT64; t += gridDim.x) {
        CP_WAIT0();
        __syncthreads();
        int next = t + gridDim.x;
        if (next < NT64) issue_tile(next * 64, cur ^ 1);

        uint32_t offH = OFF_A + cur * 55296;
        uint32_t offL = offH + 27648;
        float acc[4][4];
#pragma unroll
        for (int nf = 0; nf < 4; nf++)
#pragma unroll
            for (int r = 0; r < 4; r++) acc[nf][r] = 0.f;
#pragma unroll
        for (int c = 0; c < 3; c++) {
#pragma unroll
            for (int kk = 0; kk < 4; kk++) {
                int k0 = kk * 16;
                uint32_t ah[4], al[4], wh[2][4], wl[2][4];
                uint32_t ad = c * C64 + aRow * RSTRIDE + (k0 + aCol) * 2;
                ldsm4(ah, sb + offH + ad);
                ldsm4(al, sb + offL + ad);
#pragma unroll
                for (int nf2 = 0; nf2 < 2; nf2++) {
                    uint32_t wd = c * WCHUNK + (bRow + nf2 * 16) * RSTRIDE + (k0 + bCol) * 2;
                    ldsm4(wh[nf2], sb + OFF_WH + wd);
                    ldsm4(wl[nf2], sb + OFF_WL + wd);
                }
#pragma unroll
                for (int nf = 0; nf < 4; nf++) {
                    uint32_t* bh = &wh[nf >> 1][(nf & 1) * 2];
                    uint32_t* bl = &wl[nf >> 1][(nf & 1) * 2];
                    mma16816(acc[nf], ah, bh);
                    mma16816(acc[nf], ah, bl);
                    mma16816(acc[nf], al, bh);
                }
            }
        }
        int r0 = t * 64 + warpM * 16 + (lane >> 2);
#pragma unroll
        for (int half = 0; half < 2; half++) {
            int row = r0 + half * 8;
            if (row >= NA) continue;
#pragma unroll
            for (int nf = 0; nf < 4; nf++) {
                int col = warpN * 32 + nf * 8 + 2 * (lane & 3);
                float v0 = fmaxf(acc[nf][half * 2 + 0] + bias_s[col], 0.f);
                float v1 = fmaxf(acc[nf][half * 2 + 1] + bias_s[col + 1], 0.f);
                *(float2*)(Cf + row * HID + col) = make_float2(v0, v1);
            }
        }
        cur ^= 1;
    }
}

// ====================== fused MLP: agg@W1 -> relu -> @W2 (+stats) ==========
// 64-row tiles. X = A buf (consumed pass1, refilled during pass2), Y = h buf.
__global__ __launch_bounds__(GTHREADS, 1) void mlp_fused_kernel(
    const __nv_bfloat16* __restrict__ Ah, const __nv_bfloat16* __restrict__ Al,
    const __nv_bfloat16* __restrict__ W1h, const __nv_bfloat16* __restrict__ W1l,
    const __nv_bfloat16* __restrict__ W2h, const __nv_bfloat16* __restrict__ W2l,
    const float* __restrict__ b1, const float* __restrict__ b2,
    float* __restrict__ Cf, int slot) {
    extern __shared__ char smem[];
    const uint32_t OFF_W1H = 1024;
    const uint32_t OFF_W1L = 1024 + 2 * WCHUNK;      // 37888
    const uint32_t OFF_W2H = 1024 + 4 * WCHUNK;      // 74752
    const uint32_t OFF_W2L = 1024 + 6 * WCHUNK;      // 111616
    const uint32_t OFF_XH = 1024 + 8 * WCHUNK;       // 148480
    const uint32_t OFF_XL = OFF_XH + 2 * C64;        // 166912
    const uint32_t OFF_YH = OFF_XL + 2 * C64;        // 185344
    const uint32_t OFF_YL = OFF_YH + 2 * C64;        // 203776
    const uint32_t sb = smem_u32(smem);
    int tid = threadIdx.x;
    int wid = tid >> 5, lane = tid & 31;
    int warpM = wid & 3, warpN = wid >> 2;

    float* b1_s = (float*)smem;
    float* b2_s = (float*)(smem + 512);
    if (tid < HID) { b1_s[tid] = b1[tid]; b2_s[tid] = b2[tid]; }

    // W1 + W2 resident (128-row chunks, KC=2 each)
    for (int e = tid; e < 8192; e += GTHREADS) {
        int w2 = e / 4096, q2 = e % 4096;
        int m = q2 / 2048, q = q2 % 2048;
        int c = q >> 10, r = (q >> 3) & 127, p = q & 7;
        const __nv_bfloat16* src = w2 ? (m ? W2l : W2h) : (m ? W1l : W1h);
        uint32_t dst = w2 ? (m ? OFF_W2L : OFF_W2H) : (m ? OFF_W1L : OFF_W1H);
        uint4 v = *(const uint4*)(src + r * HID + c * 64 + p * 8);
        *(uint4*)(smem + dst + c * WCHUNK + r * RSTRIDE + p * 16) = v;
    }

    int aRow = warpM * 16 + (lane & 15);
    int aCol = (lane >> 4) * 8;
    int bRow = warpN * 32 + ((lane >> 4) * 8) + (lane & 7);
    int bCol = ((lane >> 3) & 1) * 8;

    float colSum[8], colSq[8];
#pragma unroll
    for (int j = 0; j < 8; j++) { colSum[j] = 0.f; colSq[j] = 0.f; }

    auto issue_tile = [&](int row0) {
#pragma unroll
        for (int e = tid; e < 2048; e += GTHREADS) {
            int m = e / 1024, q = e % 1024;
            int c = q >> 9, r = (q >> 3) & 63, p = q & 7;
            int grow = row0 + r;
            const __nv_bfloat16* src = m ? Al : Ah;
            int sg = grow < NA ? grow : NA - 1;
            uint32_t bytes = grow < NA ? 16u : 0u;
            uint32_t off = (m ? OFF_XL : OFF_XH) + c * C64 + r * RSTRIDE + p * 16;
            cp_async16(sb + off, src + sg * HID + c * 64 + p * 8, bytes);
        }
        CP_COMMIT();
    };

    // one 128-wide GEMM pass over the 64-row tile
    auto pass = [&](uint32_t srcH, uint32_t srcL, uint32_t offWH, uint32_t offWL,
                    float acc[4][4]) {
#pragma unroll
        for (int nf = 0; nf < 4; nf++)
#pragma unroll
            for (int r = 0; r < 4; r++) acc[nf][r] = 0.f;
#pragma unroll
        for (int c = 0; c < 2; c++) {
#pragma unroll
            for (int kk = 0; kk < 4; kk++) {
                int k0 = kk * 16;
                uint32_t ah[4], al[4], wh[2][4], wl[2][4];
                uint32_t ad = c * C64 + aRow * RSTRIDE + (k0 + aCol) * 2;
                ldsm4(ah, sb + srcH + ad);
                ldsm4(al, sb + srcL + ad);
#pragma unroll
                for (int nf2 = 0; nf2 < 2; nf2++) {
                    uint32_t wd = c * WCHUNK + (bRow + nf2 * 16) * RSTRIDE + (k0 + bCol) * 2;
                    ldsm4(wh[nf2], sb + offWH + wd);
                    ldsm4(wl[nf2], sb + offWL + wd);
                }
#pragma unroll
                for (int nf = 0; nf < 4; nf++) {
                    uint32_t* bh = &wh[nf >> 1][(nf & 1) * 2];
                    uint32_t* bl = &wl[nf >> 1][(nf & 1) * 2];
                    mma16816(acc[nf], ah, bh);
                    mma16816(acc[nf], ah, bl);
                    mma16816(acc[nf], al, bh);
                }
            }
        }
    };

    issue_tile(blockIdx.x * 64);
    for (int t = blockIdx.x; t < NT64; t += gridDim.x) {
        CP_WAIT0();
        __syncthreads();          // A(t) ready in X

        float acc[4][4];
        pass(OFF_XH, OFF_XL, OFF_W1H, OFF_W1L, acc);

        // epilogue1: h = relu(acc + b1) -> Y (bf16 hi/lo, smem)
        int lr0 = warpM * 16 + (lane >> 2);
#pragma unroll
        for (int half = 0; half < 2; half++) {
            int lrow = lr0 + half * 8;
#pragma unroll
            for (int nf = 0; nf < 4; nf++) {
                int col = warpN * 32 + nf * 8 + 2 * (lane & 3);
                float v0 = fmaxf(acc[nf][half * 2 + 0] + b1_s[col], 0.f);
                float v1 = fmaxf(acc[nf][half * 2 + 1] + b1_s[col + 1], 0.f);
                uint32_t h, l;
                split2(v0, v1, h, l);
                int c = col >> 6, cc = col & 63;
                uint32_t off = c * C64 + lrow * RSTRIDE + cc * 2;
                *(uint32_t*)(smem + OFF_YH + off) = h;
                *(uint32_t*)(smem + OFF_YL + off) = l;
            }
        }
        __syncthreads();          // Y complete; X fully consumed

        int next = t + gridDim.x;
        if (next < NT64) issue_tile(next * 64);   // refill X during pass2

        pass(OFF_YH, OFF_YL, OFF_W2H, OFF_W2L, acc);

        // epilogue2: out = acc + b2 (no relu), accumulate stats, write fp32
        int r0 = t * 64 + lr0;
#pragma unroll
        for (int half = 0; half < 2; half++) {
            int row = r0 + half * 8;
            if (row >= NA) continue;
#pragma unroll
            for (int nf = 0; nf < 4; nf++) {
                int col = warpN * 32 + nf * 8 + 2 * (lane & 3);
                float v0 = acc[nf][half * 2 + 0] + b2_s[col];
                float v1 = acc[nf][half * 2 + 1] + b2_s[col + 1];
                colSum[nf * 2] += v0;     colSq[nf * 2] += v0 * v0;
                colSum[nf * 2 + 1] += v1; colSq[nf * 2 + 1] += v1 * v1;
                *(float2*)(Cf + row * HID + col) = make_float2(v0, v1);
            }
        }
        // no bottom sync: next iteration's top sync protects X/Y reuse
    }

    // stats reduction
    __syncthreads();
    float* rs = (float*)smem;     // clobber bias area (256 floats)
    if (tid < 256) rs[tid] = 0.f;
    __syncthreads();
#pragma unroll
    for (int j = 0; j < 8; j++) {
        int col = warpN * 32 + (j >> 1) * 8 + 2 * (lane & 3) + (j & 1);
        atomicAdd(&rs[col], colSum[j]);
        atomicAdd(&rs[128 + col], colSq[j]);
    }
    __syncthreads();
    if (tid < 128) {
        atomicAdd(&g_sumA[slot][tid], rs[tid]);
        atomicAdd(&g_sumsqA[slot][tid], rs[128 + tid]);
    }
}

// ====================== pooling (+fused BN/ReLU of last depth) =============
__global__ void pool_kernel(const int* __restrict__ seg, float* __restrict__ out,
                            const float* __restrict__ gamma,
                            const float* __restrict__ beta, int slot) {
    int m = blockIdx.x;
    int t = threadIdx.x;
    const float invN = 1.f / (float)NA;
    float mean = g_sumA[slot][t] * invN;
    float var = g_sumsqA[slot][t] * invN - mean * mean;
    float sc = gamma[t] * rsqrtf(var + 1e-5f);
    float sh = beta[t] - mean * sc;
    int lo = 0, hi = NA;
    while (lo < hi) { int mid = (lo + hi) >> 1; if (seg[mid] < m) lo = mid + 1; else hi = mid; }
    int start = lo;
    hi = NA;
    while (lo < hi) { int mid = (lo + hi) >> 1; if (seg[mid] < m + 1) lo = mid + 1; else hi = mid; }
    int end = lo;
    float s = 0.f;
    for (int a = start; a < end; a++)
        s += fmaxf(fmaf(g_agg[a * HID + t], sc, sh), 0.f);
    int cnt = end - start;
    out[m * HID + t] = (cnt > 0) ? s / (float)cnt : 0.f;
}

// ====================== launch ======================
extern "C" void kernel_launch(void* const* d_in, const int* in_sizes, int n_in,
                              void* d_out, int out_size) {
    const float* f_atoms = (const float*)d_in[0];
    const float* W_in    = (const float*)d_in[1];
    const float* b_in    = (const float*)d_in[2];
    const float* W1      = (const float*)d_in[3];
    const float* b1      = (const float*)d_in[4];
    const float* W2      = (const float*)d_in[5];
    const float* b2      = (const float*)d_in[6];
    const float* gamma   = (const float*)d_in[7];
    const float* beta    = (const float*)d_in[8];
    const float* epsp    = (const float*)d_in[9];
    const int*   ei      = (const int*)d_in[10];
    const int*   seg     = (const int*)d_in[11];
    float* out = (float*)d_out;

    float *p_x, *p_agg;
    __nv_bfloat16 *p_fh, *p_fl, *p_ah, *p_al;
    __nv_bfloat16 *p_wfh, *p_wfl, *p_w1h, *p_w1l, *p_w2h, *p_w2l;
    cudaGetSymbolAddress((void**)&p_x, g_x);
    cudaGetSymbolAddress((void**)&p_agg, g_agg);
    cudaGetSymbolAddress((void**)&p_fh, g_fh);
    cudaGetSymbolAddress((void**)&p_fl, g_fl);
    cudaGetSymbolAddress((void**)&p_ah, g_ah);
    cudaGetSymbolAddress((void**)&p_al, g_al);
    cudaGetSymbolAddress((void**)&p_wfh, g_wfh);
    cudaGetSymbolAddress((void**)&p_wfl, g_wfl);
    cudaGetSymbolAddress((void**)&p_w1h, g_w1h);
    cudaGetSymbolAddress((void**)&p_w1l, g_w1l);
    cudaGetSymbolAddress((void**)&p_w2h, g_w2h);
    cudaGetSymbolAddress((void**)&p_w2l, g_w2l);

    const int SMEM_IN  = 512 + 6 * WCHUNK + 2 * 55296;   // 221696
    const int SMEM_MLP = 1024 + 8 * WCHUNK + 8 * C64;    // 222208
    cudaFuncSetAttribute(gemm_in_kernel,
                         cudaFuncAttributeMaxDynamicSharedMemorySize, SMEM_IN);
    cudaFuncSetAttribute(mlp_fused_kernel,
                         cudaFuncAttributeMaxDynamicSharedMemorySize, SMEM_MLP);

    const int EDGE_BLOCKS = (NE + 255) / 256;

    prep_weights_kernel<<<96, 256>>>(W_in, W1, W2);
    convert_atoms_kernel<<<(NA * (KPAD / 2) + 255) / 256, 256>>>(f_atoms);
    zero_csr_kernel<<<98, 1024>>>();
    gemm_in_kernel<<<148, GTHREADS, SMEM_IN>>>(p_fh, p_fl, p_wfh, p_wfl, b_in, p_x);
    count_kernel<<<EDGE_BLOCKS, 256>>>(ei);
    scan_kernel<<<1, 1024>>>();
    fill_kernel<<<EDGE_BLOCKS, 256>>>(ei);

    for (int d = 0; d < 3; d++) {
        int rslot = (d + 1) & 1;
        int zslot = d & 1;
        if (d == 0)
            gather_kernel<false><<<(NA + 7) / 8, 256>>>(p_x, epsp, d, nullptr, nullptr, 0, zslot);
        else
            gather_kernel<true><<<(NA + 7) / 8, 256>>>(p_agg, epsp, d,
                gamma + (d - 1) * HID, beta + (d - 1) * HID, rslot, zslot);
        mlp_fused_kernel<<<148, GTHREADS, SMEM_MLP>>>(
            p_ah, p_al,
            p_w1h + d * HID * HID, p_w1l + d * HID * HID,
            p_w2h + d * HID * HID, p_w2l + d * HID * HID,
            b1 + d * HID, b2 + d * HID, p_agg, zslot);
    }

    pool_kernel<<<NM, HID>>>(seg, out, gamma + 2 * HID, beta + 2 * HID, 0);
}